// round 14
// baseline (speedup 1.0000x reference)
#include <cuda_runtime.h>
#include <cuda_fp16.h>
#include <cstdint>

#define B_ 8
#define C_ 512
#define N_ 4096
#define E_ 1024
#define H_ 8
#define D_ 128

#define PL_X   (8LL*512*4096)
#define PL_WQK (2048LL*512)
#define PL_WVT (512LL*1024)
#define PL_WO  (512LL*1024)
#define PL_G   (8LL*512*512)
#define PL_A1  (8LL*1024*512)
#define PL_ATT (8LL*8*128*128)
#define PL_MT  (8LL*512*1024)
#define PL_F   (8LL*512*512)

__device__ __half g_x2  [2*PL_X];
__device__ __half g_wqk2[2*PL_WQK];
__device__ __half g_wvt2[2*PL_WVT];
__device__ __half g_wo2 [2*PL_WO];
__device__ __half g_G2  [2*PL_G];
__device__ __half g_A12 [2*PL_A1];
__device__ __half g_att2[2*PL_ATT];
__device__ __half g_mt2 [2*PL_MT];
__device__ __half g_F2  [2*PL_F];
__device__ float g_Gp  [8*B_*C_*C_];
__device__ float g_lraw[4*B_*H_*D_*D_];
__device__ float g_part[B_*C_*128];
__device__ float g_s [B_*C_];
__device__ float g_t [B_*3*E_];
__device__ float g_cv[B_*E_];
__device__ float g_g [B_*C_];

__device__ __forceinline__ uint32_t smem_u32(const void* p){
    uint32_t a;
    asm("{ .reg .u64 t; cvta.to.shared.u64 t, %1; cvt.u32.u64 %0, t; }":"=r"(a):"l"(p));
    return a;
}
#define CP16(dst, src) asm volatile("cp.async.cg.shared.global [%0], [%1], 16;"::"r"(dst),"l"(src))
#define CP_COMMIT() asm volatile("cp.async.commit_group;")
#define CP_WAIT1() asm volatile("cp.async.wait_group 1;")
#define CP_WAIT0() asm volatile("cp.async.wait_group 0;")
#define LDSM4(R, A) \
    asm volatile("ldmatrix.sync.aligned.m8n8.x4.shared.b16 {%0,%1,%2,%3}, [%4];" \
        : "=r"((R)[0]),"=r"((R)[1]),"=r"((R)[2]),"=r"((R)[3]) : "r"(A))
#define LDSM4T(R, A) \
    asm volatile("ldmatrix.sync.aligned.m8n8.x4.trans.shared.b16 {%0,%1,%2,%3}, [%4];" \
        : "=r"((R)[0]),"=r"((R)[1]),"=r"((R)[2]),"=r"((R)[3]) : "r"(A))
#define MMA(C, A, B0, B1) \
    asm volatile("mma.sync.aligned.m16n8k16.row.col.f32.f16.f16.f32 " \
        "{%0,%1,%2,%3}, {%4,%5,%6,%7}, {%8,%9}, {%0,%1,%2,%3};" \
        : "+f"((C)[0]),"+f"((C)[1]),"+f"((C)[2]),"+f"((C)[3]) \
        : "r"((A)[0]),"r"((A)[1]),"r"((A)[2]),"r"((A)[3]), "r"(B0),"r"(B1))

// ---------------------------------------------------------------------------
// fp16-split GEMM, 128x128 CTA tile, BK=32, 256 thr, warp 64x32, 2-stage
// cp.async, 2 CTAs/SM. TRB: B is (K,N), ldmatrix.trans.
// NPROD=3: hh+hl+lh. NPROD=2: hh+hl. SYM: upper-tri tiles of 512x512.
// OUTP 0: fp32 (+bias row if HB). OUTP 1: 2-plane fp16 split out.
// ZBi = K-split: piece zi covers chunks [zi*nch/ZBi, (zi+1)*nch/ZBi).
// ---------------------------------------------------------------------------
#define PITCH 80
#define PLB (128*PITCH)
#define BUFB (4*PLB)
#define PITCHB 272
#define PLBB (32*PITCHB)

template <int OUTP, bool HB, int NPROD, bool SYM, bool TRB>
__global__ void __launch_bounds__(256, 2)
hgemm(const __half* __restrict__ A, const __half* __restrict__ B,
      void* __restrict__ Cv, const float* __restrict__ bias,
      int K, int lda, int ldb, int ldc,
      long long planeA, long long planeB, long long planeC,
      long long sAo, long long sAm,
      long long sBo, long long sBm,
      long long sCo, long long sCm, long long sCi,
      long long sBias, int ZBm, int ZBi)
{
    extern __shared__ char smem[];
    const uint32_t sb = smem_u32(smem);
    const int tid = threadIdx.x, wid = tid>>5, lane = tid&31;
    const int z = blockIdx.z;
    const int zo = z/(ZBm*ZBi);
    const int zr = z - zo*ZBm*ZBi;
    const int zm = zr/ZBi;
    const int zi = zr - zm*ZBi;
    A += zo*sAo + zm*sAm;
    B += zo*sBo + zm*sBm;
    const long long co = zo*sCo + zm*sCm + zi*sCi;

    int bx = blockIdx.x, by = blockIdx.y;
    if (SYM){
        int i = blockIdx.x;
        int tx = 0;
        while (((tx+1)*(tx+2))/2 <= i) tx++;
        by = i - (tx*(tx+1))/2;
        bx = tx;
    }
    const int row0 = by*128, col0 = bx*128;

    const __half* gp[4] = {A, A+planeA, B, B+planeB};
    const int gld[4]  = {lda, lda, ldb, ldb};
    const int gr0[4]  = {row0, row0, col0, col0};

    const int wm0 = (wid&1)*64;
    const int wn0 = (wid>>1)*32;

    int aoff[4], boff[2];
    int boffT = 0;
#pragma unroll
    for (int mt=0; mt<4; mt++){
        int r = wm0 + mt*16 + ((lane>>3)&1)*8 + (lane&7);
        aoff[mt] = r*PITCH + ((lane>>4)&1)*16;
    }
    if (TRB){
        boffT = (((lane>>3)&1)*8 + (lane&7))*PITCHB + wn0*2 + ((lane>>4)&1)*16;
    } else {
#pragma unroll
        for (int ng=0; ng<2; ng++){
            int r = wn0 + ng*16 + ((lane>>4)&1)*8 + (lane&7);
            boff[ng] = r*PITCH + ((lane>>3)&1)*16;
        }
    }

    float acc[4][4][4];
#pragma unroll
    for (int i=0;i<4;i++)
#pragma unroll
        for (int j=0;j<4;j++)
#pragma unroll
            for (int k=0;k<4;k++) acc[i][j][k]=0.f;

#define LOADCH(CH, BUF) do{ \
    int kk = (CH)<<5; \
    _Pragma("unroll") \
    for (int p=0;p<4;p++){ \
        if (NPROD==2 && p==1) continue; \
        if (TRB && p>=2){ \
            _Pragma("unroll") \
            for (int j=0;j<2;j++){ \
                int idx = j*256 + tid; \
                int r = idx>>4, c = idx&15; \
                uint32_t dst = sb + (BUF)*BUFB + 2*PLB + (p-2)*PLBB + r*PITCHB + c*16; \
                const __half* src = gp[p] + (long long)(kk+r)*gld[p] + col0 + c*8; \
                CP16(dst, src); \
            } \
        } else { \
            _Pragma("unroll") \
            for (int j=0;j<2;j++){ \
                int idx = j*256 + tid; \
                int r = idx>>2, c = idx&3; \
                uint32_t dst = sb + (BUF)*BUFB + p*PLB + r*PITCH + c*16; \
                const __half* src = gp[p] + (long long)(gr0[p]+r)*gld[p] + kk + c*8; \
                CP16(dst, src); \
            } \
        } \
    } \
}while(0)

    const int nchT = K>>5;
    const int c0 = (zi*nchT)/ZBi;
    const int c1 = ((zi+1)*nchT)/ZBi;

    LOADCH(c0,0); CP_COMMIT();

    for (int ch=c0; ch<c1; ++ch){
        const int bufi = (ch-c0)&1;
        if (ch+1 < c1){
            LOADCH(ch+1, bufi^1); CP_COMMIT();
            CP_WAIT1();
        } else {
            CP_WAIT0();
        }
        __syncthreads();

        const uint32_t bufb = sb + bufi*BUFB;
#pragma unroll
        for (int ks=0; ks<2; ks++){
            uint32_t af0[4][4], af1[4][4], bf[2][2][4];
            // phase 1: A-hi + both B planes (8 LDSM exposed)
#pragma unroll
            for (int mt=0;mt<4;mt++)
                LDSM4(af0[mt], bufb + 0*PLB + aoff[mt] + ks*32);
#pragma unroll
            for (int p=0;p<2;p++)
#pragma unroll
                for (int ng=0;ng<2;ng++){
                    if (TRB)
                        LDSM4T(bf[p][ng], bufb + 2*PLB + p*PLBB + boffT + ks*(16*PITCHB) + ng*32);
                    else
                        LDSM4(bf[p][ng], bufb + (2+p)*PLB + boff[ng] + ks*32);
                }
            // hh
#pragma unroll
            for (int mt=0;mt<4;mt++)
#pragma unroll
                for (int nt=0;nt<4;nt++)
                    MMA(acc[mt][nt], af0[mt], bf[0][nt>>1][(nt&1)*2], bf[0][nt>>1][(nt&1)*2+1]);
            // phase 2: A-lo loads hidden under hh burst
            if (NPROD==3)
#pragma unroll
                for (int mt=0;mt<4;mt++)
                    LDSM4(af1[mt], bufb + 1*PLB + aoff[mt] + ks*32);
            // hl
#pragma unroll
            for (int mt=0;mt<4;mt++)
#pragma unroll
                for (int nt=0;nt<4;nt++)
                    MMA(acc[mt][nt], af0[mt], bf[1][nt>>1][(nt&1)*2], bf[1][nt>>1][(nt&1)*2+1]);
            // lh
            if (NPROD==3)
#pragma unroll
                for (int mt=0;mt<4;mt++)
#pragma unroll
                    for (int nt=0;nt<4;nt++)
                        MMA(acc[mt][nt], af1[mt], bf[0][nt>>1][(nt&1)*2], bf[0][nt>>1][(nt&1)*2+1]);
        }
        __syncthreads();
    }

    // epilogue
#pragma unroll
    for (int mt=0;mt<4;mt++){
#pragma unroll
        for (int nt=0;nt<4;nt++){
            int r0 = row0 + wm0 + mt*16 + (lane>>2);
            int cb = col0 + wn0 + nt*8 + (lane&3)*2;
            if (OUTP == 0){
                float* Cf = (float*)Cv + co;
                float b0 = HB ? bias[(long long)zo*sBias + r0]     : 0.f;
                float b1 = HB ? bias[(long long)zo*sBias + r0 + 8] : 0.f;
                *(float2*)(Cf + (long long)r0*ldc + cb) =
                    make_float2(acc[mt][nt][0]+b0, acc[mt][nt][1]+b0);
                *(float2*)(Cf + (long long)(r0+8)*ldc + cb) =
                    make_float2(acc[mt][nt][2]+b1, acc[mt][nt][3]+b1);
            } else {
                __half* Ch = (__half*)Cv + co;
#pragma unroll
                for (int hrow=0; hrow<2; hrow++){
                    long long o = (long long)(r0 + hrow*8)*ldc + cb;
                    float v0 = acc[mt][nt][hrow*2], v1 = acc[mt][nt][hrow*2+1];
                    __half h0 = __float2half_rn(v0), h1 = __float2half_rn(v1);
                    __half l0 = __float2half_rn(v0-__half2float(h0));
                    __half l1 = __float2half_rn(v1-__half2float(h1));
                    *(__half2*)(Ch + o) = __halves2half2(h0,h1);
                    *(__half2*)(Ch + planeC + o) = __halves2half2(l0,l1);
                }
            }
        }
    }
#undef LOADCH
}

// ---------------------------------------------------------------------------
// Gram reduce: sum 3 fp32 split-K partials (upper tiles), split fp16 h/l,
// mirror lower triangle. grid (16, 10, 8), block (32,8)
// ---------------------------------------------------------------------------
__global__ void gram_reduce(const float* __restrict__ P, __half* __restrict__ G2)
{
    const int RY[10]={0,0,1,0,1,2,0,1,2,3};
    const int CX[10]={0,1,1,2,2,2,3,3,3,3};
    const int t = blockIdx.y, b = blockIdx.z;
    const int r0 = RY[t]*128 + (blockIdx.x>>2)*32;
    const int c0 = CX[t]*128 + (blockIdx.x&3)*32;
    const long long CC = (long long)C_*C_;
    const long long S = (long long)B_*CC;
    const float* Pb = P + (long long)b*CC;
    __half* Gb = G2 + (long long)b*CC;
    __shared__ __half th[32][33], tl_[32][33];
    const int x = threadIdx.x, y = threadIdx.y;
#pragma unroll
    for (int i=0;i<4;i++){
        int r = r0 + y + 8*i;
        long long o = (long long)r*C_ + c0 + x;
        float v = Pb[o] + Pb[S + o] + Pb[2*S + o];
        __half h = __float2half_rn(v);
        __half l = __float2half_rn(v - __half2float(h));
        Gb[o] = h;
        Gb[PL_G + o] = l;
        th[y+8*i][x] = h;
        tl_[y+8*i][x] = l;
    }
    __syncthreads();
    if (RY[t] != CX[t]){
#pragma unroll
        for (int i=0;i<4;i++){
            long long o = (long long)(c0+y+8*i)*C_ + r0 + x;
            Gb[o] = th[x][y+8*i];
            Gb[PL_G + o] = tl_[x][y+8*i];
        }
    }
}

// F reduce: sum 2 fp32 partials -> F2 h/l planes.
__global__ void freduce(const float* __restrict__ P, __half* __restrict__ F2)
{
    const long long S = (long long)B_*C_*C_;
    long long i = ((long long)blockIdx.x*256 + threadIdx.x)*4;
    if (i >= S) return;
    float4 a = *(const float4*)(P+i);
    float4 b = *(const float4*)(P+S+i);
    float vv[4] = {a.x+b.x, a.y+b.y, a.z+b.z, a.w+b.w};
    __half h[4], l[4];
#pragma unroll
    for (int j=0;j<4;j++){
        h[j] = __float2half_rn(vv[j]);
        l[j] = __float2half_rn(vv[j]-__half2float(h[j]));
    }
    *(__half2*)(F2+i)   = __halves2half2(h[0],h[1]);
    *(__half2*)(F2+i+2) = __halves2half2(h[2],h[3]);
    *(__half2*)(F2+PL_F+i)   = __halves2half2(l[0],l[1]);
    *(__half2*)(F2+PL_F+i+2) = __halves2half2(l[2],l[3]);
}

// ---------------------------------------------------------------------------
// x prep: x -> x2 h/l + rowsum partials. grid (8, 256, 8), block 256
// ---------------------------------------------------------------------------
__global__ void xprep_kernel(const float* __restrict__ x, __half* __restrict__ x2,
                             float* __restrict__ part)
{
    const int b = blockIdx.z;
    const long long boff = (long long)b*C_*N_;
    const int rr = threadIdx.x >> 7;
    const int c  = blockIdx.y*2 + rr;
    const int n0 = blockIdx.x*512 + (threadIdx.x & 127)*4;
    long long o = boff + (long long)c*N_ + n0;
    float4 v = *(const float4*)(x + o);
    __half h0=__float2half_rn(v.x), h1=__float2half_rn(v.y);
    __half h2=__float2half_rn(v.z), h3=__float2half_rn(v.w);
    *(__half2*)(x2+o)   = __halves2half2(h0,h1);
    *(__half2*)(x2+o+2) = __halves2half2(h2,h3);
    *(__half2*)(x2+PL_X+o) =
        __halves2half2(__float2half_rn(v.x-__half2float(h0)),
                       __float2half_rn(v.y-__half2float(h1)));
    *(__half2*)(x2+PL_X+o+2) =
        __halves2half2(__float2half_rn(v.z-__half2float(h2)),
                       __float2half_rn(v.w-__half2float(h3)));
    float rs = v.x + v.y + v.z + v.w;
    const int lane = threadIdx.x & 31;
#pragma unroll
    for (int of=16; of; of>>=1) rs += __shfl_xor_sync(0xffffffffu, rs, of);
    if (!lane){
        int wseg = (threadIdx.x & 127) >> 5;
        part[((long long)(b*C_ + c) << 5) | (blockIdx.x*4 + wseg)] = rs;
    }
}

__global__ void rowsum_reduce(const float* __restrict__ part, float* __restrict__ s)
{
    const int row = blockIdx.x;
    float v = part[((long long)row << 5) | threadIdx.x];
#pragma unroll
    for (int of=16; of; of>>=1) v += __shfl_xor_sync(0xffffffffu, v, of);
    if (!threadIdx.x) s[row] = v;
}

// ---------------------------------------------------------------------------
// Fused: split w_qkv rows 0..2047 (q,k) h/l AND t[b][r] = dot(w_row, s[b]).
// ---------------------------------------------------------------------------
__global__ void wqkv_split_dot(const float* __restrict__ w, const float* __restrict__ s,
                               __half* __restrict__ wqk2, float* __restrict__ t)
{
    const int rr = threadIdx.x >> 7;
    const int r  = blockIdx.x*2 + rr;
    const int ct = (threadIdx.x & 127)*4;
    float4 v = *(const float4*)(w + (long long)r*C_ + ct);

    __half h0=__float2half_rn(v.x), h1=__float2half_rn(v.y);
    __half h2=__float2half_rn(v.z), h3=__float2half_rn(v.w);
    long long o = (long long)r*C_ + ct;
    *(__half2*)(wqk2+o)   = __halves2half2(h0,h1);
    *(__half2*)(wqk2+o+2) = __halves2half2(h2,h3);
    *(__half2*)(wqk2+PL_WQK+o) =
        __halves2half2(__float2half_rn(v.x-__half2float(h0)),
                       __float2half_rn(v.y-__half2float(h1)));
    *(__half2*)(wqk2+PL_WQK+o+2) =
        __halves2half2(__float2half_rn(v.z-__half2float(h2)),
                       __float2half_rn(v.w-__half2float(h3)));

    const int wid = threadIdx.x>>5, lane = threadIdx.x&31;
    __shared__ float sh[8][8];
#pragma unroll
    for (int b=0;b<8;b++){
        float4 sv = *(const float4*)(s + b*C_ + ct);
        float p = v.x*sv.x + v.y*sv.y + v.z*sv.z + v.w*sv.w;
#pragma unroll
        for (int of=16; of; of>>=1) p += __shfl_xor_sync(0xffffffffu, p, of);
        if (!lane) sh[wid][b] = p;
    }
    __syncthreads();
    if (threadIdx.x < 16){
        int r2 = threadIdx.x>>3;
        int b  = threadIdx.x&7;
        float tv = sh[r2*4][b]+sh[r2*4+1][b]+sh[r2*4+2][b]+sh[r2*4+3][b];
        t[b*(3*E_) + blockIdx.x*2 + r2] = tv;
    }
}

// ---------------- conversions (weights) ----------------
__global__ void split2h(const float* __restrict__ s, __half* __restrict__ d,
                        long long plane, long long n)
{
    long long i = ((long long)blockIdx.x*256 + threadIdx.x)*4;
    if (i >= n) return;
    float4 v = *(const float4*)(s+i);
    float vv[4] = {v.x,v.y,v.z,v.w};
    __half h[4], l[4];
#pragma unroll
    for (int j=0;j<4;j++){
        h[j] = __float2half_rn(vv[j]);
        l[j] = __float2half_rn(vv[j]-__half2float(h[j]));
    }
    *(__half2*)(d+i)   = __halves2half2(h[0],h[1]);
    *(__half2*)(d+i+2) = __halves2half2(h[2],h[3]);
    *(__half2*)(d+plane+i)   = __halves2half2(l[0],l[1]);
    *(__half2*)(d+plane+i+2) = __halves2half2(l[2],l[3]);
}

__global__ void tsplit2h(const float* __restrict__ src, __half* __restrict__ dst,
                         int R, int Cc, long long plane, long long ssz, long long dsz)
{
    __shared__ float t[32][33];
    const int z = blockIdx.z;
    src += (long long)z*ssz; dst += (long long)z*dsz;
    const int c0 = blockIdx.x*32, r0 = blockIdx.y*32;
    const int x = threadIdx.x, y = threadIdx.y;
#pragma unroll
    for (int i=0;i<4;i++)
        t[y+8*i][x] = src[(long long)(r0+y+8*i)*Cc + c0 + x];
    __syncthreads();
#pragma unroll
    for (int i=0;i<4;i++){
        float v = t[x][y+8*i];
        __half h = __float2half_rn(v);
        long long o = (long long)(c0+y+8*i)*R + r0 + x;
        dst[o] = h;
        dst[plane+o] = __float2half_rn(v-__half2float(h));
    }
}

// ---------------- small kernels ----------------
__global__ void softmax_kernel(const float* __restrict__ lraw, const float* __restrict__ tvec,
                               const float* __restrict__ bqkv, const float* __restrict__ mask,
                               __half* __restrict__ att2, float* __restrict__ cvec)
{
    const int idx = blockIdx.x;
    const int d = idx&127, h = (idx>>7)&7, b = idx>>10;
    const int e = threadIdx.x;
    const long long base = (long long)idx*D_;
    const long long S = (long long)B_*H_*D_*D_;

    const float bq = bqkv[h*D_+d];
    const float bk = bqkv[E_+h*D_+e];
    const float qt = tvec[b*(3*E_)+h*D_+d];
    const float kt = tvec[b*(3*E_)+E_+h*D_+e];
    float L = lraw[base+e] + lraw[S+base+e] + lraw[2*S+base+e] + lraw[3*S+base+e]
            + bq*kt + bk*qt + (float)N_*bq*bk;

    __shared__ float sh[128];
    sh[e]=L; __syncthreads();
    for (int st=64;st;st>>=1){ if(e<st) sh[e]=fmaxf(sh[e],sh[e+st]); __syncthreads(); }
    const float mx = sh[0]; __syncthreads();
    const float ex = expf(L-mx);
    sh[e]=ex; __syncthreads();
    for (int st=64;st;st>>=1){ if(e<st) sh[e]+=sh[e+st]; __syncthreads(); }
    const float inv = 1.f/sh[0]; __syncthreads();
    const float m = (mask[base+e] < 0.1f) ? 1.f : 0.f;
    const float p = ex*inv*m;

    __half hh = __float2half_rn(p);
    att2[base+e] = hh;
    att2[PL_ATT+base+e] = __float2half_rn(p-__half2float(hh));

    sh[e] = p*bqkv[2*E_+h*D_+e]; __syncthreads();
    for (int st=64;st;st>>=1){ if(e<st) sh[e]+=sh[e+st]; __syncthreads(); }
    if (!e) cvec[b*E_+h*D_+d]=sh[0];
}
__global__ void gvec_kernel(const float* __restrict__ wout, const float* __restrict__ cvec,
                            const float* __restrict__ bout, float* __restrict__ g)
{
    const int cc = blockIdx.x, b = threadIdx.x>>5, lane = threadIdx.x&31;
    const float* wr = wout + (long long)cc*E_;
    const float* cv = cvec + b*E_;
    float acc = 0.f;
    for (int i=lane;i<E_;i+=32) acc += wr[i]*cv[i];
    for (int o=16;o;o>>=1) acc += __shfl_xor_sync(0xffffffffu,acc,o);
    if (!lane) g[b*C_+cc]=acc+bout[cc];
}

// ---------------- launch ----------------
extern "C" void kernel_launch(void* const* d_in, const int* in_sizes, int n_in,
                              void* d_out, int out_size)
{
    const float* x     = (const float*)d_in[0];
    const float* w_qkv = (const float*)d_in[1];
    const float* b_qkv = (const float*)d_in[2];
    const float* w_out = (const float*)d_in[3];
    const float* b_out = (const float*)d_in[4];
    const float* mask  = (const float*)d_in[5];
    float* out = (float*)d_out;

    __half *x2,*wqk2,*wvt2,*wo2,*G2,*A12,*att2,*mt2,*F2;
    float *Gp,*lraw,*part,*s,*t,*cv,*g;
    cudaGetSymbolAddress((void**)&x2,  g_x2);
    cudaGetSymbolAddress((void**)&wqk2,g_wqk2);
    cudaGetSymbolAddress((void**)&wvt2,g_wvt2);
    cudaGetSymbolAddress((void**)&wo2, g_wo2);
    cudaGetSymbolAddress((void**)&G2,  g_G2);
    cudaGetSymbolAddress((void**)&A12, g_A12);
    cudaGetSymbolAddress((void**)&att2,g_att2);
    cudaGetSymbolAddress((void**)&mt2, g_mt2);
    cudaGetSymbolAddress((void**)&F2,  g_F2);
    cudaGetSymbolAddress((void**)&Gp,  g_Gp);
    cudaGetSymbolAddress((void**)&lraw,g_lraw);
    cudaGetSymbolAddress((void**)&part,g_part);
    cudaGetSymbolAddress((void**)&s,   g_s);
    cudaGetSymbolAddress((void**)&t,   g_t);
    cudaGetSymbolAddress((void**)&cv,  g_cv);
    cudaGetSymbolAddress((void**)&g,   g_g);

    const int SMB = 2*BUFB;   // 81920 (2 CTAs/SM)
    cudaFuncSetAttribute(hgemm<0,false,3,true ,false>, cudaFuncAttributeMaxDynamicSharedMemorySize, SMB);
    cudaFuncSetAttribute(hgemm<1,false,3,false,false>, cudaFuncAttributeMaxDynamicSharedMemorySize, SMB);
    cudaFuncSetAttribute(hgemm<0,false,3,false,false>, cudaFuncAttributeMaxDynamicSharedMemorySize, SMB);
    cudaFuncSetAttribute(hgemm<1,false,2,false,false>, cudaFuncAttributeMaxDynamicSharedMemorySize, SMB);
    cudaFuncSetAttribute(hgemm<0,false,2,false,false>, cudaFuncAttributeMaxDynamicSharedMemorySize, SMB);
    cudaFuncSetAttribute(hgemm<0,true ,2,false,true >, cudaFuncAttributeMaxDynamicSharedMemorySize, SMB);

    const long long CN = (long long)C_*N_;
    const long long CC = (long long)C_*C_;
    const long long EC = (long long)E_*C_;
    const long long DD = (long long)D_*D_;
    const long long DC = (long long)D_*C_;
    const long long S  = (long long)B_*H_*DD;

    // prep
    xprep_kernel<<<dim3(N_/512, C_/2, B_), 256>>>(x, x2, part);
    rowsum_reduce<<<B_*C_, 32>>>(part, s);
    wqkv_split_dot<<<1024, 256>>>(w_qkv, s, wqk2, t);

    // Gram partials: upper tiles, split-K=3 (z = b*3 + ks), single wave
    hgemm<0,false,3,true,false><<<dim3(10,1,B_*3), 256, SMB>>>(
        x2, x2, Gp, nullptr, N_, N_, N_, C_,
        PL_X, PL_X, 0,
        0, CN,
        0, CN,
        0, CC, (long long)B_*CC,
        0, B_, 3);
    gram_reduce<<<dim3(16,10,B_), dim3(32,8)>>>(Gp, G2);

    // A1[b] = Wq @ G[b]
    hgemm<1,false,3,false,false><<<dim3(4,8,B_), 256, SMB>>>(
        wqk2, G2, A12, nullptr, C_, C_, C_, C_,
        PL_WQK, PL_G, PL_A1,
        0,0, CC,0, EC,0,0,
        0, 1, 1);

    // logits partials: z = (b*H + h)*4 + ks
    hgemm<0,false,3,false,false><<<dim3(1,1,B_*H_*4), 256, SMB>>>(
        A12, wqk2 + (long long)E_*C_, lraw, nullptr, C_, C_, C_, D_,
        PL_A1, PL_WQK, 0,
        EC, DC,
        0,  DC,
        (long long)H_*DD, DD, S,
        0, H_, 4);

    // off-path weight conversions (needed from MT onward)
    split2h<<<(int)(PL_WO/4/256), 256>>>(w_out, wo2, PL_WO, PL_WO);
    tsplit2h<<<dim3(C_/32, E_/32, 1), dim3(32,8)>>>(w_qkv + 2LL*E_*C_, wvt2, E_, C_, PL_WVT, 0, 0);

    softmax_kernel<<<B_*H_*D_, 128>>>(lraw, t, b_qkv, mask, att2, cv);

    // MT[b][c, h*128+d] = sum_e WvT[c, h*128+e] * att_h[d,e]   (2-prod)
    hgemm<1,false,2,false,false><<<dim3(1,4,B_*H_), 256, SMB>>>(
        wvt2, att2, mt2, nullptr, D_, E_, D_, E_,
        PL_WVT, PL_ATT, PL_MT,
        0, 128,
        (long long)H_*DD, DD,
        (long long)C_*E_, 128, 0,
        0, H_, 1);

    gvec_kernel<<<C_, 256>>>(w_out, cv, b_out, g);

    // F partials: split-K=2 (z = b*2 + ks), fp32 out into Gp
    hgemm<0,false,2,false,false><<<dim3(4,4,B_*2), 256, SMB>>>(
        wo2, mt2, Gp, nullptr, E_, E_, E_, C_,
        PL_WO, PL_MT, 0,
        0, 0,
        (long long)C_*E_, 0,
        CC, 0, (long long)B_*CC,
        0, 1, 2);
    freduce<<<(int)((B_*CC/4 + 255)/256), 256>>>(Gp, F2);

    // out[b] = F[b] @ x[b] + g   (TN: B = x2 directly, ldmatrix.trans)
    hgemm<0,true,2,false,true><<<dim3(32,4,B_), 256, SMB>>>(
        F2, x2, out, g, C_, C_, N_, N_,
        PL_F, PL_X, 0,
        CC,0, CN,0, CN,0,0,
        C_, 1, 1);
}

// round 15
// speedup vs baseline: 1.0003x; 1.0003x over previous
#include <cuda_runtime.h>
#include <cuda_fp16.h>
#include <cstdint>

#define B_ 8
#define C_ 512
#define N_ 4096
#define E_ 1024
#define H_ 8
#define D_ 128

#define PL_X   (8LL*512*4096)
#define PL_WQK (2048LL*512)
#define PL_WVT (512LL*1024)
#define PL_WO  (512LL*1024)
#define PL_G   (8LL*512*512)
#define PL_A1  (8LL*1024*512)
#define PL_ATT (8LL*8*128*128)
#define PL_MT  (8LL*512*1024)
#define PL_F   (8LL*512*512)

__device__ __half g_x2  [2*PL_X];
__device__ __half g_wqk2[2*PL_WQK];
__device__ __half g_wvt2[2*PL_WVT];
__device__ __half g_wo2 [2*PL_WO];
__device__ __half g_G2  [2*PL_G];
__device__ __half g_A12 [2*PL_A1];
__device__ __half g_att2[2*PL_ATT];
__device__ __half g_mt2 [2*PL_MT];
__device__ __half g_F2  [2*PL_F];
__device__ float g_Gp  [8*B_*C_*C_];
__device__ float g_lraw[4*B_*H_*D_*D_];
__device__ float g_part[B_*C_*128];
__device__ float g_s [B_*C_];
__device__ float g_t [B_*3*E_];
__device__ float g_cv[B_*E_];
__device__ float g_g [B_*C_];

__device__ __forceinline__ uint32_t smem_u32(const void* p){
    uint32_t a;
    asm("{ .reg .u64 t; cvta.to.shared.u64 t, %1; cvt.u32.u64 %0, t; }":"=r"(a):"l"(p));
    return a;
}
#define CP16(dst, src) asm volatile("cp.async.cg.shared.global [%0], [%1], 16;"::"r"(dst),"l"(src))
#define CP_COMMIT() asm volatile("cp.async.commit_group;")
#define CP_WAIT2() asm volatile("cp.async.wait_group 2;")
#define CP_WAIT1() asm volatile("cp.async.wait_group 1;")
#define CP_WAIT0() asm volatile("cp.async.wait_group 0;")
#define LDSM4(R, A) \
    asm volatile("ldmatrix.sync.aligned.m8n8.x4.shared.b16 {%0,%1,%2,%3}, [%4];" \
        : "=r"((R)[0]),"=r"((R)[1]),"=r"((R)[2]),"=r"((R)[3]) : "r"(A))
#define LDSM4T(R, A) \
    asm volatile("ldmatrix.sync.aligned.m8n8.x4.trans.shared.b16 {%0,%1,%2,%3}, [%4];" \
        : "=r"((R)[0]),"=r"((R)[1]),"=r"((R)[2]),"=r"((R)[3]) : "r"(A))
#define MMA(C, A, B0, B1) \
    asm volatile("mma.sync.aligned.m16n8k16.row.col.f32.f16.f16.f32 " \
        "{%0,%1,%2,%3}, {%4,%5,%6,%7}, {%8,%9}, {%0,%1,%2,%3};" \
        : "+f"((C)[0]),"+f"((C)[1]),"+f"((C)[2]),"+f"((C)[3]) \
        : "r"((A)[0]),"r"((A)[1]),"r"((A)[2]),"r"((A)[3]), "r"(B0),"r"(B1))

// ---------------------------------------------------------------------------
// fp16-split GEMM, 128x128 CTA tile, BK=32, 256 thr, warp 64x32, 2 CTAs/SM.
// NPROD=3: hh+hl+lh (4 smem planes, 2-stage). NPROD=2: hh+hl (3 planes, 3-stage).
// TRB: B is (K,N), ldmatrix.trans. SYM: upper-tri tiles of 512x512.
// OUTP 0: fp32 (+bias row if HB). OUTP 1: 2-plane fp16 split out.
// ZBi = K-split: piece zi covers chunks [zi*nch/ZBi, (zi+1)*nch/ZBi).
// ---------------------------------------------------------------------------
#define PITCH 80
#define PLB (128*PITCH)
#define PITCHB 272
#define PLBB (32*PITCHB)

template <int OUTP, bool HB, int NPROD, bool SYM, bool TRB>
__global__ void __launch_bounds__(256, 2)
hgemm(const __half* __restrict__ A, const __half* __restrict__ B,
      void* __restrict__ Cv, const float* __restrict__ bias,
      int K, int lda, int ldb, int ldc,
      long long planeA, long long planeB, long long planeC,
      long long sAo, long long sAm,
      long long sBo, long long sBm,
      long long sCo, long long sCm, long long sCi,
      long long sBias, int ZBm, int ZBi)
{
    constexpr int NSTAGE = (NPROD==2) ? 3 : 2;
    constexpr int BBASE  = (NPROD==3) ? 2*PLB : PLB;
    constexpr int SBP    = TRB ? PLBB : PLB;
    constexpr int BUFS   = BBASE + 2*SBP;

    extern __shared__ char smem[];
    const uint32_t sb = smem_u32(smem);
    const int tid = threadIdx.x, wid = tid>>5, lane = tid&31;
    const int z = blockIdx.z;
    const int zo = z/(ZBm*ZBi);
    const int zr = z - zo*ZBm*ZBi;
    const int zm = zr/ZBi;
    const int zi = zr - zm*ZBi;
    A += zo*sAo + zm*sAm;
    B += zo*sBo + zm*sBm;
    const long long co = zo*sCo + zm*sCm + zi*sCi;

    int bx = blockIdx.x, by = blockIdx.y;
    if (SYM){
        int i = blockIdx.x;
        int tx = 0;
        while (((tx+1)*(tx+2))/2 <= i) tx++;
        by = i - (tx*(tx+1))/2;
        bx = tx;
    }
    const int row0 = by*128, col0 = bx*128;

    const __half* gp[4] = {A, A+planeA, B, B+planeB};
    const int gld[4]  = {lda, lda, ldb, ldb};
    const int gr0[4]  = {row0, row0, col0, col0};

    const int wm0 = (wid&1)*64;
    const int wn0 = (wid>>1)*32;

    int aoff[4], boff[2];
    int boffT = 0;
#pragma unroll
    for (int mt=0; mt<4; mt++){
        int r = wm0 + mt*16 + ((lane>>3)&1)*8 + (lane&7);
        aoff[mt] = r*PITCH + ((lane>>4)&1)*16;
    }
    if (TRB){
        boffT = (((lane>>3)&1)*8 + (lane&7))*PITCHB + wn0*2 + ((lane>>4)&1)*16;
    } else {
#pragma unroll
        for (int ng=0; ng<2; ng++){
            int r = wn0 + ng*16 + ((lane>>4)&1)*8 + (lane&7);
            boff[ng] = r*PITCH + ((lane>>3)&1)*16;
        }
    }

    float acc[4][4][4];
#pragma unroll
    for (int i=0;i<4;i++)
#pragma unroll
        for (int j=0;j<4;j++)
#pragma unroll
            for (int k=0;k<4;k++) acc[i][j][k]=0.f;

#define LOADCH(CH, BUF) do{ \
    int kk = (CH)<<5; \
    _Pragma("unroll") \
    for (int p=0;p<4;p++){ \
        if (NPROD==2 && p==1) continue; \
        const int slot = (p==0)?0 : (p==1)?PLB : BBASE + (p-2)*SBP; \
        if (TRB && p>=2){ \
            _Pragma("unroll") \
            for (int j=0;j<2;j++){ \
                int idx = j*256 + tid; \
                int r = idx>>4, c = idx&15; \
                uint32_t dst = sb + (BUF)*BUFS + slot + r*PITCHB + c*16; \
                const __half* src = gp[p] + (long long)(kk+r)*gld[p] + col0 + c*8; \
                CP16(dst, src); \
            } \
        } else { \
            _Pragma("unroll") \
            for (int j=0;j<2;j++){ \
                int idx = j*256 + tid; \
                int r = idx>>2, c = idx&3; \
                uint32_t dst = sb + (BUF)*BUFS + slot + r*PITCH + c*16; \
                const __half* src = gp[p] + (long long)(gr0[p]+r)*gld[p] + kk + c*8; \
                CP16(dst, src); \
            } \
        } \
    } \
}while(0)

    const int nchT = K>>5;
    const int c0 = (zi*nchT)/ZBi;
    const int c1 = ((zi+1)*nchT)/ZBi;

    LOADCH(c0,0); CP_COMMIT();
    if (NSTAGE==3 && c0+1 < c1){ LOADCH(c0+1,1); CP_COMMIT(); }

    for (int ch=c0; ch<c1; ++ch){
        const int bufi = (ch-c0)%NSTAGE;
        if (NSTAGE==3){
            if (ch+2 < c1){
                LOADCH(ch+2, (ch-c0+2)%3); CP_COMMIT();
                CP_WAIT2();
            } else if (ch+1 < c1) CP_WAIT1();
            else CP_WAIT0();
        } else {
            if (ch+1 < c1){
                LOADCH(ch+1, bufi^1); CP_COMMIT();
                CP_WAIT1();
            } else CP_WAIT0();
        }
        __syncthreads();

        const uint32_t bufb = sb + bufi*BUFS;
#pragma unroll
        for (int ks=0; ks<2; ks++){
            uint32_t af0[4][4], af1[4][4], bf[2][2][4];
#pragma unroll
            for (int mt=0;mt<4;mt++)
                LDSM4(af0[mt], bufb + aoff[mt] + ks*32);
#pragma unroll
            for (int p=0;p<2;p++)
#pragma unroll
                for (int ng=0;ng<2;ng++){
                    if (TRB)
                        LDSM4T(bf[p][ng], bufb + BBASE + p*SBP + boffT + ks*(16*PITCHB) + ng*32);
                    else
                        LDSM4(bf[p][ng], bufb + BBASE + p*SBP + boff[ng] + ks*32);
                }
            // hh
#pragma unroll
            for (int mt=0;mt<4;mt++)
#pragma unroll
                for (int nt=0;nt<4;nt++)
                    MMA(acc[mt][nt], af0[mt], bf[0][nt>>1][(nt&1)*2], bf[0][nt>>1][(nt&1)*2+1]);
            // A-lo loads hidden under hh burst
            if (NPROD==3)
#pragma unroll
                for (int mt=0;mt<4;mt++)
                    LDSM4(af1[mt], bufb + PLB + aoff[mt] + ks*32);
            // hl
#pragma unroll
            for (int mt=0;mt<4;mt++)
#pragma unroll
                for (int nt=0;nt<4;nt++)
                    MMA(acc[mt][nt], af0[mt], bf[1][nt>>1][(nt&1)*2], bf[1][nt>>1][(nt&1)*2+1]);
            // lh
            if (NPROD==3)
#pragma unroll
                for (int mt=0;mt<4;mt++)
#pragma unroll
                    for (int nt=0;nt<4;nt++)
                        MMA(acc[mt][nt], af1[mt], bf[0][nt>>1][(nt&1)*2], bf[0][nt>>1][(nt&1)*2+1]);
        }
        __syncthreads();
    }

    // epilogue
#pragma unroll
    for (int mt=0;mt<4;mt++){
#pragma unroll
        for (int nt=0;nt<4;nt++){
            int r0 = row0 + wm0 + mt*16 + (lane>>2);
            int cb = col0 + wn0 + nt*8 + (lane&3)*2;
            if (OUTP == 0){
                float* Cf = (float*)Cv + co;
                float b0 = HB ? bias[(long long)zo*sBias + r0]     : 0.f;
                float b1 = HB ? bias[(long long)zo*sBias + r0 + 8] : 0.f;
                *(float2*)(Cf + (long long)r0*ldc + cb) =
                    make_float2(acc[mt][nt][0]+b0, acc[mt][nt][1]+b0);
                *(float2*)(Cf + (long long)(r0+8)*ldc + cb) =
                    make_float2(acc[mt][nt][2]+b1, acc[mt][nt][3]+b1);
            } else {
                __half* Ch = (__half*)Cv + co;
#pragma unroll
                for (int hrow=0; hrow<2; hrow++){
                    long long o = (long long)(r0 + hrow*8)*ldc + cb;
                    float v0 = acc[mt][nt][hrow*2], v1 = acc[mt][nt][hrow*2+1];
                    __half h0 = __float2half_rn(v0), h1 = __float2half_rn(v1);
                    __half l0 = __float2half_rn(v0-__half2float(h0));
                    __half l1 = __float2half_rn(v1-__half2float(h1));
                    *(__half2*)(Ch + o) = __halves2half2(h0,h1);
                    *(__half2*)(Ch + planeC + o) = __halves2half2(l0,l1);
                }
            }
        }
    }
#undef LOADCH
}

// ---------------------------------------------------------------------------
// Gram reduce: sum 8 fp32 split-K partials (upper tiles), split fp16 h/l,
// mirror lower triangle. grid (16, 10, 8), block (32,8)
// ---------------------------------------------------------------------------
__global__ void gram_reduce(const float* __restrict__ P, __half* __restrict__ G2)
{
    const int RY[10]={0,0,1,0,1,2,0,1,2,3};
    const int CX[10]={0,1,1,2,2,2,3,3,3,3};
    const int t = blockIdx.y, b = blockIdx.z;
    const int r0 = RY[t]*128 + (blockIdx.x>>2)*32;
    const int c0 = CX[t]*128 + (blockIdx.x&3)*32;
    const long long CC = (long long)C_*C_;
    const long long S = (long long)B_*CC;
    const float* Pb = P + (long long)b*CC;
    __half* Gb = G2 + (long long)b*CC;
    __shared__ __half th[32][33], tl_[32][33];
    const int x = threadIdx.x, y = threadIdx.y;
#pragma unroll
    for (int i=0;i<4;i++){
        int r = r0 + y + 8*i;
        long long o = (long long)r*C_ + c0 + x;
        float v = 0.f;
#pragma unroll
        for (int p=0;p<8;p++) v += Pb[p*S + o];
        __half h = __float2half_rn(v);
        __half l = __float2half_rn(v - __half2float(h));
        Gb[o] = h;
        Gb[PL_G + o] = l;
        th[y+8*i][x] = h;
        tl_[y+8*i][x] = l;
    }
    __syncthreads();
    if (RY[t] != CX[t]){
#pragma unroll
        for (int i=0;i<4;i++){
            long long o = (long long)(c0+y+8*i)*C_ + r0 + x;
            Gb[o] = th[x][y+8*i];
            Gb[PL_G + o] = tl_[x][y+8*i];
        }
    }
}

// F reduce: sum 2 fp32 partials -> F2 h/l planes.
__global__ void freduce(const float* __restrict__ P, __half* __restrict__ F2)
{
    const long long S = (long long)B_*C_*C_;
    long long i = ((long long)blockIdx.x*256 + threadIdx.x)*4;
    if (i >= S) return;
    float4 a = *(const float4*)(P+i);
    float4 b = *(const float4*)(P+S+i);
    float vv[4] = {a.x+b.x, a.y+b.y, a.z+b.z, a.w+b.w};
    __half h[4], l[4];
#pragma unroll
    for (int j=0;j<4;j++){
        h[j] = __float2half_rn(vv[j]);
        l[j] = __float2half_rn(vv[j]-__half2float(h[j]));
    }
    *(__half2*)(F2+i)   = __halves2half2(h[0],h[1]);
    *(__half2*)(F2+i+2) = __halves2half2(h[2],h[3]);
    *(__half2*)(F2+PL_F+i)   = __halves2half2(l[0],l[1]);
    *(__half2*)(F2+PL_F+i+2) = __halves2half2(l[2],l[3]);
}

// ---------------------------------------------------------------------------
// x prep: x -> x2 h/l + rowsum partials. grid (8, 256, 8), block 256
// ---------------------------------------------------------------------------
__global__ void xprep_kernel(const float* __restrict__ x, __half* __restrict__ x2,
                             float* __restrict__ part)
{
    const int b = blockIdx.z;
    const long long boff = (long long)b*C_*N_;
    const int rr = threadIdx.x >> 7;
    const int c  = blockIdx.y*2 + rr;
    const int n0 = blockIdx.x*512 + (threadIdx.x & 127)*4;
    long long o = boff + (long long)c*N_ + n0;
    float4 v = *(const float4*)(x + o);
    __half h0=__float2half_rn(v.x), h1=__float2half_rn(v.y);
    __half h2=__float2half_rn(v.z), h3=__float2half_rn(v.w);
    *(__half2*)(x2+o)   = __halves2half2(h0,h1);
    *(__half2*)(x2+o+2) = __halves2half2(h2,h3);
    *(__half2*)(x2+PL_X+o) =
        __halves2half2(__float2half_rn(v.x-__half2float(h0)),
                       __float2half_rn(v.y-__half2float(h1)));
    *(__half2*)(x2+PL_X+o+2) =
        __halves2half2(__float2half_rn(v.z-__half2float(h2)),
                       __float2half_rn(v.w-__half2float(h3)));
    float rs = v.x + v.y + v.z + v.w;
    const int lane = threadIdx.x & 31;
#pragma unroll
    for (int of=16; of; of>>=1) rs += __shfl_xor_sync(0xffffffffu, rs, of);
    if (!lane){
        int wseg = (threadIdx.x & 127) >> 5;
        part[((long long)(b*C_ + c) << 5) | (blockIdx.x*4 + wseg)] = rs;
    }
}

__global__ void rowsum_reduce(const float* __restrict__ part, float* __restrict__ s)
{
    const int row = blockIdx.x;
    float v = part[((long long)row << 5) | threadIdx.x];
#pragma unroll
    for (int of=16; of; of>>=1) v += __shfl_xor_sync(0xffffffffu, v, of);
    if (!threadIdx.x) s[row] = v;
}

// ---------------------------------------------------------------------------
// Fused: split w_qkv rows 0..2047 (q,k) h/l AND t[b][r] = dot(w_row, s[b]).
// ---------------------------------------------------------------------------
__global__ void wqkv_split_dot(const float* __restrict__ w, const float* __restrict__ s,
                               __half* __restrict__ wqk2, float* __restrict__ t)
{
    const int rr = threadIdx.x >> 7;
    const int r  = blockIdx.x*2 + rr;
    const int ct = (threadIdx.x & 127)*4;
    float4 v = *(const float4*)(w + (long long)r*C_ + ct);

    __half h0=__float2half_rn(v.x), h1=__float2half_rn(v.y);
    __half h2=__float2half_rn(v.z), h3=__float2half_rn(v.w);
    long long o = (long long)r*C_ + ct;
    *(__half2*)(wqk2+o)   = __halves2half2(h0,h1);
    *(__half2*)(wqk2+o+2) = __halves2half2(h2,h3);
    *(__half2*)(wqk2+PL_WQK+o) =
        __halves2half2(__float2half_rn(v.x-__half2float(h0)),
                       __float2half_rn(v.y-__half2float(h1)));
    *(__half2*)(wqk2+PL_WQK+o+2) =
        __halves2half2(__float2half_rn(v.z-__half2float(h2)),
                       __float2half_rn(v.w-__half2float(h3)));

    const int wid = threadIdx.x>>5, lane = threadIdx.x&31;
    __shared__ float sh[8][8];
#pragma unroll
    for (int b=0;b<8;b++){
        float4 sv = *(const float4*)(s + b*C_ + ct);
        float p = v.x*sv.x + v.y*sv.y + v.z*sv.z + v.w*sv.w;
#pragma unroll
        for (int of=16; of; of>>=1) p += __shfl_xor_sync(0xffffffffu, p, of);
        if (!lane) sh[wid][b] = p;
    }
    __syncthreads();
    if (threadIdx.x < 16){
        int r2 = threadIdx.x>>3;
        int b  = threadIdx.x&7;
        float tv = sh[r2*4][b]+sh[r2*4+1][b]+sh[r2*4+2][b]+sh[r2*4+3][b];
        t[b*(3*E_) + blockIdx.x*2 + r2] = tv;
    }
}

// ---------------- conversions (weights) ----------------
__global__ void split2h(const float* __restrict__ s, __half* __restrict__ d,
                        long long plane, long long n)
{
    long long i = ((long long)blockIdx.x*256 + threadIdx.x)*4;
    if (i >= n) return;
    float4 v = *(const float4*)(s+i);
    float vv[4] = {v.x,v.y,v.z,v.w};
    __half h[4], l[4];
#pragma unroll
    for (int j=0;j<4;j++){
        h[j] = __float2half_rn(vv[j]);
        l[j] = __float2half_rn(vv[j]-__half2float(h[j]));
    }
    *(__half2*)(d+i)   = __halves2half2(h[0],h[1]);
    *(__half2*)(d+i+2) = __halves2half2(h[2],h[3]);
    *(__half2*)(d+plane+i)   = __halves2half2(l[0],l[1]);
    *(__half2*)(d+plane+i+2) = __halves2half2(l[2],l[3]);
}

__global__ void tsplit2h(const float* __restrict__ src, __half* __restrict__ dst,
                         int R, int Cc, long long plane, long long ssz, long long dsz)
{
    __shared__ float t[32][33];
    const int z = blockIdx.z;
    src += (long long)z*ssz; dst += (long long)z*dsz;
    const int c0 = blockIdx.x*32, r0 = blockIdx.y*32;
    const int x = threadIdx.x, y = threadIdx.y;
#pragma unroll
    for (int i=0;i<4;i++)
        t[y+8*i][x] = src[(long long)(r0+y+8*i)*Cc + c0 + x];
    __syncthreads();
#pragma unroll
    for (int i=0;i<4;i++){
        float v = t[x][y+8*i];
        __half h = __float2half_rn(v);
        long long o = (long long)(c0+y+8*i)*R + r0 + x;
        dst[o] = h;
        dst[plane+o] = __float2half_rn(v-__half2float(h));
    }
}

// ---------------- small kernels ----------------
__global__ void softmax_kernel(const float* __restrict__ lraw, const float* __restrict__ tvec,
                               const float* __restrict__ bqkv, const float* __restrict__ mask,
                               __half* __restrict__ att2, float* __restrict__ cvec)
{
    const int idx = blockIdx.x;
    const int d = idx&127, h = (idx>>7)&7, b = idx>>10;
    const int e = threadIdx.x;
    const long long base = (long long)idx*D_;
    const long long S = (long long)B_*H_*D_*D_;

    const float bq = bqkv[h*D_+d];
    const float bk = bqkv[E_+h*D_+e];
    const float qt = tvec[b*(3*E_)+h*D_+d];
    const float kt = tvec[b*(3*E_)+E_+h*D_+e];
    float L = lraw[base+e] + lraw[S+base+e] + lraw[2*S+base+e] + lraw[3*S+base+e]
            + bq*kt + bk*qt + (float)N_*bq*bk;

    __shared__ float sh[128];
    sh[e]=L; __syncthreads();
    for (int st=64;st;st>>=1){ if(e<st) sh[e]=fmaxf(sh[e],sh[e+st]); __syncthreads(); }
    const float mx = sh[0]; __syncthreads();
    const float ex = expf(L-mx);
    sh[e]=ex; __syncthreads();
    for (int st=64;st;st>>=1){ if(e<st) sh[e]+=sh[e+st]; __syncthreads(); }
    const float inv = 1.f/sh[0]; __syncthreads();
    const float m = (mask[base+e] < 0.1f) ? 1.f : 0.f;
    const float p = ex*inv*m;

    __half hh = __float2half_rn(p);
    att2[base+e] = hh;
    att2[PL_ATT+base+e] = __float2half_rn(p-__half2float(hh));

    sh[e] = p*bqkv[2*E_+h*D_+e]; __syncthreads();
    for (int st=64;st;st>>=1){ if(e<st) sh[e]+=sh[e+st]; __syncthreads(); }
    if (!e) cvec[b*E_+h*D_+d]=sh[0];
}
__global__ void gvec_kernel(const float* __restrict__ wout, const float* __restrict__ cvec,
                            const float* __restrict__ bout, float* __restrict__ g)
{
    const int cc = blockIdx.x, b = threadIdx.x>>5, lane = threadIdx.x&31;
    const float* wr = wout + (long long)cc*E_;
    const float* cv = cvec + b*E_;
    float acc = 0.f;
    for (int i=lane;i<E_;i+=32) acc += wr[i]*cv[i];
    for (int o=16;o;o>>=1) acc += __shfl_xor_sync(0xffffffffu,acc,o);
    if (!lane) g[b*C_+cc]=acc+bout[cc];
}

// ---------------- launch ----------------
extern "C" void kernel_launch(void* const* d_in, const int* in_sizes, int n_in,
                              void* d_out, int out_size)
{
    const float* x     = (const float*)d_in[0];
    const float* w_qkv = (const float*)d_in[1];
    const float* b_qkv = (const float*)d_in[2];
    const float* w_out = (const float*)d_in[3];
    const float* b_out = (const float*)d_in[4];
    const float* mask  = (const float*)d_in[5];
    float* out = (float*)d_out;

    __half *x2,*wqk2,*wvt2,*wo2,*G2,*A12,*att2,*mt2,*F2;
    float *Gp,*lraw,*part,*s,*t,*cv,*g;
    cudaGetSymbolAddress((void**)&x2,  g_x2);
    cudaGetSymbolAddress((void**)&wqk2,g_wqk2);
    cudaGetSymbolAddress((void**)&wvt2,g_wvt2);
    cudaGetSymbolAddress((void**)&wo2, g_wo2);
    cudaGetSymbolAddress((void**)&G2,  g_G2);
    cudaGetSymbolAddress((void**)&A12, g_A12);
    cudaGetSymbolAddress((void**)&att2,g_att2);
    cudaGetSymbolAddress((void**)&mt2, g_mt2);
    cudaGetSymbolAddress((void**)&F2,  g_F2);
    cudaGetSymbolAddress((void**)&Gp,  g_Gp);
    cudaGetSymbolAddress((void**)&lraw,g_lraw);
    cudaGetSymbolAddress((void**)&part,g_part);
    cudaGetSymbolAddress((void**)&s,   g_s);
    cudaGetSymbolAddress((void**)&t,   g_t);
    cudaGetSymbolAddress((void**)&cv,  g_cv);
    cudaGetSymbolAddress((void**)&g,   g_g);

    const int SMB3  = 2*4*PLB;              // 81920  (NPROD3, 2-stage)
    const int SMB2N = 3*3*PLB;              // 92160  (NPROD2 NT, 3-stage)
    const int SMB2T = 3*(PLB + 2*PLBB);     // 82944  (NPROD2 TRB, 3-stage)
    cudaFuncSetAttribute(hgemm<0,false,3,true ,false>, cudaFuncAttributeMaxDynamicSharedMemorySize, SMB3);
    cudaFuncSetAttribute(hgemm<1,false,3,false,false>, cudaFuncAttributeMaxDynamicSharedMemorySize, SMB3);
    cudaFuncSetAttribute(hgemm<0,false,3,false,false>, cudaFuncAttributeMaxDynamicSharedMemorySize, SMB3);
    cudaFuncSetAttribute(hgemm<1,false,2,false,false>, cudaFuncAttributeMaxDynamicSharedMemorySize, SMB2N);
    cudaFuncSetAttribute(hgemm<0,false,2,false,false>, cudaFuncAttributeMaxDynamicSharedMemorySize, SMB2N);
    cudaFuncSetAttribute(hgemm<0,true ,2,false,true >, cudaFuncAttributeMaxDynamicSharedMemorySize, SMB2T);

    const long long CN = (long long)C_*N_;
    const long long CC = (long long)C_*C_;
    const long long EC = (long long)E_*C_;
    const long long DD = (long long)D_*D_;
    const long long DC = (long long)D_*C_;
    const long long S  = (long long)B_*H_*DD;

    // prep
    xprep_kernel<<<dim3(N_/512, C_/2, B_), 256>>>(x, x2, part);
    rowsum_reduce<<<B_*C_, 32>>>(part, s);
    wqkv_split_dot<<<1024, 256>>>(w_qkv, s, wqk2, t);

    // Gram partials: upper tiles, split-K=8 (z = b*8 + ks)
    hgemm<0,false,3,true,false><<<dim3(10,1,B_*8), 256, SMB3>>>(
        x2, x2, Gp, nullptr, N_, N_, N_, C_,
        PL_X, PL_X, 0,
        0, CN,
        0, CN,
        0, CC, (long long)B_*CC,
        0, B_, 8);
    gram_reduce<<<dim3(16,10,B_), dim3(32,8)>>>(Gp, G2);

    // A1[b] = Wq @ G[b]
    hgemm<1,false,3,false,false><<<dim3(4,8,B_), 256, SMB3>>>(
        wqk2, G2, A12, nullptr, C_, C_, C_, C_,
        PL_WQK, PL_G, PL_A1,
        0,0, CC,0, EC,0,0,
        0, 1, 1);

    // logits partials: z = (b*H + h)*4 + ks
    hgemm<0,false,3,false,false><<<dim3(1,1,B_*H_*4), 256, SMB3>>>(
        A12, wqk2 + (long long)E_*C_, lraw, nullptr, C_, C_, C_, D_,
        PL_A1, PL_WQK, 0,
        EC, DC,
        0,  DC,
        (long long)H_*DD, DD, S,
        0, H_, 4);

    // off-path weight conversions (needed from MT onward)
    split2h<<<(int)(PL_WO/4/256), 256>>>(w_out, wo2, PL_WO, PL_WO);
    tsplit2h<<<dim3(C_/32, E_/32, 1), dim3(32,8)>>>(w_qkv + 2LL*E_*C_, wvt2, E_, C_, PL_WVT, 0, 0);

    softmax_kernel<<<B_*H_*D_, 128>>>(lraw, t, b_qkv, mask, att2, cv);

    // MT[b][c, h*128+d] = sum_e WvT[c, h*128+e] * att_h[d,e]   (2-prod, 3-stage)
    hgemm<1,false,2,false,false><<<dim3(1,4,B_*H_), 256, SMB2N>>>(
        wvt2, att2, mt2, nullptr, D_, E_, D_, E_,
        PL_WVT, PL_ATT, PL_MT,
        0, 128,
        (long long)H_*DD, DD,
        (long long)C_*E_, 128, 0,
        0, H_, 1);

    gvec_kernel<<<C_, 256>>>(w_out, cv, b_out, g);

    // F partials: split-K=2 (z = b*2 + ks), fp32 out into Gp (2-prod, 3-stage)
    hgemm<0,false,2,false,false><<<dim3(4,4,B_*2), 256, SMB2N>>>(
        wo2, mt2, Gp, nullptr, E_, E_, E_, C_,
        PL_WO, PL_MT, 0,
        0, 0,
        (long long)C_*E_, 0,
        CC, 0, (long long)B_*CC,
        0, 1, 2);
    freduce<<<(int)((B_*CC/4 + 255)/256), 256>>>(Gp, F2);

    // out[b] = F[b] @ x[b] + g   (TN, 2-prod, 3-stage)
    hgemm<0,true,2,false,true><<<dim3(32,4,B_), 256, SMB2T>>>(
        F2, x2, out, g, C_, C_, N_, N_,
        PL_F, PL_X, 0,
        CC,0, CN,0, CN,0,0,
        C_, 1, 1);
}

// round 16
// speedup vs baseline: 1.1178x; 1.1175x over previous
#include <cuda_runtime.h>
#include <cuda_fp16.h>
#include <cstdint>

#define B_ 8
#define C_ 512
#define N_ 4096
#define E_ 1024
#define H_ 8
#define D_ 128

#define PL_X   (8LL*512*4096)
#define PL_WQK (2048LL*512)
#define PL_WVT (512LL*1024)
#define PL_WO  (512LL*1024)
#define PL_G   (8LL*512*512)
#define PL_A1  (8LL*1024*512)
#define PL_ATT (8LL*8*128*128)
#define PL_MT  (8LL*512*1024)
#define PL_F   (8LL*512*512)

__device__ __half g_x2  [2*PL_X];
__device__ __half g_wqk2[2*PL_WQK];
__device__ __half g_wvt2[2*PL_WVT];
__device__ __half g_wo2 [2*PL_WO];
__device__ __half g_G2  [2*PL_G];
__device__ __half g_A12 [2*PL_A1];
__device__ __half g_att2[2*PL_ATT];
__device__ __half g_mt2 [2*PL_MT];
__device__ __half g_F2  [2*PL_F];
__device__ float g_Gp  [8*B_*C_*C_];
__device__ float g_lraw[4*B_*H_*D_*D_];
__device__ float g_part[B_*C_*128];
__device__ float g_s [B_*C_];
__device__ float g_t [B_*3*E_];
__device__ float g_cv[B_*E_];
__device__ float g_g [B_*C_];

__device__ __forceinline__ uint32_t smem_u32(const void* p){
    uint32_t a;
    asm("{ .reg .u64 t; cvta.to.shared.u64 t, %1; cvt.u32.u64 %0, t; }":"=r"(a):"l"(p));
    return a;
}
#define CP16(dst, src) asm volatile("cp.async.cg.shared.global [%0], [%1], 16;"::"r"(dst),"l"(src))
#define CP_COMMIT() asm volatile("cp.async.commit_group;")
#define CP_WAIT2() asm volatile("cp.async.wait_group 2;")
#define CP_WAIT1() asm volatile("cp.async.wait_group 1;")
#define CP_WAIT0() asm volatile("cp.async.wait_group 0;")
#define LDSM4(R, A) \
    asm volatile("ldmatrix.sync.aligned.m8n8.x4.shared.b16 {%0,%1,%2,%3}, [%4];" \
        : "=r"((R)[0]),"=r"((R)[1]),"=r"((R)[2]),"=r"((R)[3]) : "r"(A))
#define LDSM4T(R, A) \
    asm volatile("ldmatrix.sync.aligned.m8n8.x4.trans.shared.b16 {%0,%1,%2,%3}, [%4];" \
        : "=r"((R)[0]),"=r"((R)[1]),"=r"((R)[2]),"=r"((R)[3]) : "r"(A))
#define MMA(C, A, B0, B1) \
    asm volatile("mma.sync.aligned.m16n8k16.row.col.f32.f16.f16.f32 " \
        "{%0,%1,%2,%3}, {%4,%5,%6,%7}, {%8,%9}, {%0,%1,%2,%3};" \
        : "+f"((C)[0]),"+f"((C)[1]),"+f"((C)[2]),"+f"((C)[3]) \
        : "r"((A)[0]),"r"((A)[1]),"r"((A)[2]),"r"((A)[3]), "r"(B0),"r"(B1))

// ---------------------------------------------------------------------------
// fp16-split GEMM, 128x128 CTA tile, BK=32, 256 thr, warp 64x32, 2 CTAs/SM.
// NPROD=3: hh+hl+lh (4 planes, 2-stage). NPROD=2: hh+hl (3 planes, 3-stage).
// NPROD=1: hh only (2 planes, 3-stage).
// TRB: B is (K,N), ldmatrix.trans. SYM: upper-tri tiles of 512x512.
// OUTP 0: fp32 (+bias row if HB). OUTP 1: 2-plane fp16 split out.
// ZBi = K-split: piece zi covers chunks [zi*nch/ZBi, (zi+1)*nch/ZBi).
// ---------------------------------------------------------------------------
#define PITCH 80
#define PLB (128*PITCH)
#define PITCHB 272
#define PLBB (32*PITCHB)

template <int OUTP, bool HB, int NPROD, bool SYM, bool TRB>
__global__ void __launch_bounds__(256, 2)
hgemm(const __half* __restrict__ A, const __half* __restrict__ B,
      void* __restrict__ Cv, const float* __restrict__ bias,
      int K, int lda, int ldb, int ldc,
      long long planeA, long long planeB, long long planeC,
      long long sAo, long long sAm,
      long long sBo, long long sBm,
      long long sCo, long long sCm, long long sCi,
      long long sBias, int ZBm, int ZBi)
{
    constexpr int NSTAGE = (NPROD<=2) ? 3 : 2;
    constexpr int NBPL   = (NPROD==1) ? 1 : 2;        // B planes
    constexpr int BBASE  = (NPROD==3) ? 2*PLB : PLB;  // A planes bytes
    constexpr int SBP    = TRB ? PLBB : PLB;
    constexpr int BUFS   = BBASE + NBPL*SBP;

    extern __shared__ char smem[];
    const uint32_t sb = smem_u32(smem);
    const int tid = threadIdx.x, wid = tid>>5, lane = tid&31;
    const int z = blockIdx.z;
    const int zo = z/(ZBm*ZBi);
    const int zr = z - zo*ZBm*ZBi;
    const int zm = zr/ZBi;
    const int zi = zr - zm*ZBi;
    A += zo*sAo + zm*sAm;
    B += zo*sBo + zm*sBm;
    const long long co = zo*sCo + zm*sCm + zi*sCi;

    int bx = blockIdx.x, by = blockIdx.y;
    if (SYM){
        int i = blockIdx.x;
        int tx = 0;
        while (((tx+1)*(tx+2))/2 <= i) tx++;
        by = i - (tx*(tx+1))/2;
        bx = tx;
    }
    const int row0 = by*128, col0 = bx*128;

    const __half* gp[4] = {A, A+planeA, B, B+planeB};
    const int gld[4]  = {lda, lda, ldb, ldb};
    const int gr0[4]  = {row0, row0, col0, col0};

    const int wm0 = (wid&1)*64;
    const int wn0 = (wid>>1)*32;

    int aoff[4], boff[2];
    int boffT = 0;
#pragma unroll
    for (int mt=0; mt<4; mt++){
        int r = wm0 + mt*16 + ((lane>>3)&1)*8 + (lane&7);
        aoff[mt] = r*PITCH + ((lane>>4)&1)*16;
    }
    if (TRB){
        boffT = (((lane>>3)&1)*8 + (lane&7))*PITCHB + wn0*2 + ((lane>>4)&1)*16;
    } else {
#pragma unroll
        for (int ng=0; ng<2; ng++){
            int r = wn0 + ng*16 + ((lane>>4)&1)*8 + (lane&7);
            boff[ng] = r*PITCH + ((lane>>3)&1)*16;
        }
    }

    float acc[4][4][4];
#pragma unroll
    for (int i=0;i<4;i++)
#pragma unroll
        for (int j=0;j<4;j++)
#pragma unroll
            for (int k=0;k<4;k++) acc[i][j][k]=0.f;

#define LOADCH(CH, BUF) do{ \
    int kk = (CH)<<5; \
    _Pragma("unroll") \
    for (int p=0;p<4;p++){ \
        if (NPROD<=2 && p==1) continue; \
        if (NPROD==1 && p==3) continue; \
        const int slot = (p==0)?0 : (p==1)?PLB : BBASE + (p-2)*SBP; \
        if (TRB && p>=2){ \
            _Pragma("unroll") \
            for (int j=0;j<2;j++){ \
                int idx = j*256 + tid; \
                int r = idx>>4, c = idx&15; \
                uint32_t dst = sb + (BUF)*BUFS + slot + r*PITCHB + c*16; \
                const __half* src = gp[p] + (long long)(kk+r)*gld[p] + col0 + c*8; \
                CP16(dst, src); \
            } \
        } else { \
            _Pragma("unroll") \
            for (int j=0;j<2;j++){ \
                int idx = j*256 + tid; \
                int r = idx>>2, c = idx&3; \
                uint32_t dst = sb + (BUF)*BUFS + slot + r*PITCH + c*16; \
                const __half* src = gp[p] + (long long)(gr0[p]+r)*gld[p] + kk + c*8; \
                CP16(dst, src); \
            } \
        } \
    } \
}while(0)

    const int nchT = K>>5;
    const int c0 = (zi*nchT)/ZBi;
    const int c1 = ((zi+1)*nchT)/ZBi;

    LOADCH(c0,0); CP_COMMIT();
    if (NSTAGE==3 && c0+1 < c1){ LOADCH(c0+1,1); CP_COMMIT(); }

    for (int ch=c0; ch<c1; ++ch){
        const int bufi = (ch-c0)%NSTAGE;
        if (NSTAGE==3){
            if (ch+2 < c1){
                LOADCH(ch+2, (ch-c0+2)%3); CP_COMMIT();
                CP_WAIT2();
            } else if (ch+1 < c1) CP_WAIT1();
            else CP_WAIT0();
        } else {
            if (ch+1 < c1){
                LOADCH(ch+1, bufi^1); CP_COMMIT();
                CP_WAIT1();
            } else CP_WAIT0();
        }
        __syncthreads();

        const uint32_t bufb = sb + bufi*BUFS;
#pragma unroll
        for (int ks=0; ks<2; ks++){
            uint32_t af0[4][4], af1[4][4], bf[2][2][4];
#pragma unroll
            for (int mt=0;mt<4;mt++)
                LDSM4(af0[mt], bufb + aoff[mt] + ks*32);
#pragma unroll
            for (int p=0;p<NBPL;p++)
#pragma unroll
                for (int ng=0;ng<2;ng++){
                    if (TRB)
                        LDSM4T(bf[p][ng], bufb + BBASE + p*SBP + boffT + ks*(16*PITCHB) + ng*32);
                    else
                        LDSM4(bf[p][ng], bufb + BBASE + p*SBP + boff[ng] + ks*32);
                }
            // hh
#pragma unroll
            for (int mt=0;mt<4;mt++)
#pragma unroll
                for (int nt=0;nt<4;nt++)
                    MMA(acc[mt][nt], af0[mt], bf[0][nt>>1][(nt&1)*2], bf[0][nt>>1][(nt&1)*2+1]);
            // A-lo loads hidden under hh burst
            if (NPROD==3)
#pragma unroll
                for (int mt=0;mt<4;mt++)
                    LDSM4(af1[mt], bufb + PLB + aoff[mt] + ks*32);
            // hl
            if (NPROD>=2)
#pragma unroll
                for (int mt=0;mt<4;mt++)
#pragma unroll
                    for (int nt=0;nt<4;nt++)
                        MMA(acc[mt][nt], af0[mt], bf[1][nt>>1][(nt&1)*2], bf[1][nt>>1][(nt&1)*2+1]);
            // lh
            if (NPROD==3)
#pragma unroll
                for (int mt=0;mt<4;mt++)
#pragma unroll
                    for (int nt=0;nt<4;nt++)
                        MMA(acc[mt][nt], af1[mt], bf[0][nt>>1][(nt&1)*2], bf[0][nt>>1][(nt&1)*2+1]);
        }
        __syncthreads();
    }

    // epilogue
#pragma unroll
    for (int mt=0;mt<4;mt++){
#pragma unroll
        for (int nt=0;nt<4;nt++){
            int r0 = row0 + wm0 + mt*16 + (lane>>2);
            int cb = col0 + wn0 + nt*8 + (lane&3)*2;
            if (OUTP == 0){
                float* Cf = (float*)Cv + co;
                float b0 = HB ? bias[(long long)zo*sBias + r0]     : 0.f;
                float b1 = HB ? bias[(long long)zo*sBias + r0 + 8] : 0.f;
                *(float2*)(Cf + (long long)r0*ldc + cb) =
                    make_float2(acc[mt][nt][0]+b0, acc[mt][nt][1]+b0);
                *(float2*)(Cf + (long long)(r0+8)*ldc + cb) =
                    make_float2(acc[mt][nt][2]+b1, acc[mt][nt][3]+b1);
            } else {
                __half* Ch = (__half*)Cv + co;
#pragma unroll
                for (int hrow=0; hrow<2; hrow++){
                    long long o = (long long)(r0 + hrow*8)*ldc + cb;
                    float v0 = acc[mt][nt][hrow*2], v1 = acc[mt][nt][hrow*2+1];
                    __half h0 = __float2half_rn(v0), h1 = __float2half_rn(v1);
                    __half l0 = __float2half_rn(v0-__half2float(h0));
                    __half l1 = __float2half_rn(v1-__half2float(h1));
                    *(__half2*)(Ch + o) = __halves2half2(h0,h1);
                    *(__half2*)(Ch + planeC + o) = __halves2half2(l0,l1);
                }
            }
        }
    }
#undef LOADCH
}

// ---------------------------------------------------------------------------
// Gram reduce: sum 8 fp32 split-K partials (upper tiles), split fp16 h/l,
// mirror lower triangle. grid (16, 10, 8), block (32,8)
// ---------------------------------------------------------------------------
__global__ void gram_reduce(const float* __restrict__ P, __half* __restrict__ G2)
{
    const int RY[10]={0,0,1,0,1,2,0,1,2,3};
    const int CX[10]={0,1,1,2,2,2,3,3,3,3};
    const int t = blockIdx.y, b = blockIdx.z;
    const int r0 = RY[t]*128 + (blockIdx.x>>2)*32;
    const int c0 = CX[t]*128 + (blockIdx.x&3)*32;
    const long long CC = (long long)C_*C_;
    const long long S = (long long)B_*CC;
    const float* Pb = P + (long long)b*CC;
    __half* Gb = G2 + (long long)b*CC;
    __shared__ __half th[32][33], tl_[32][33];
    const int x = threadIdx.x, y = threadIdx.y;
#pragma unroll
    for (int i=0;i<4;i++){
        int r = r0 + y + 8*i;
        long long o = (long long)r*C_ + c0 + x;
        float v = 0.f;
#pragma unroll
        for (int p=0;p<8;p++) v += Pb[p*S + o];
        __half h = __float2half_rn(v);
        __half l = __float2half_rn(v - __half2float(h));
        Gb[o] = h;
        Gb[PL_G + o] = l;
        th[y+8*i][x] = h;
        tl_[y+8*i][x] = l;
    }
    __syncthreads();
    if (RY[t] != CX[t]){
#pragma unroll
        for (int i=0;i<4;i++){
            long long o = (long long)(c0+y+8*i)*C_ + r0 + x;
            Gb[o] = th[x][y+8*i];
            Gb[PL_G + o] = tl_[x][y+8*i];
        }
    }
}

// F reduce: sum 2 fp32 partials -> F2 h/l planes.
__global__ void freduce(const float* __restrict__ P, __half* __restrict__ F2)
{
    const long long S = (long long)B_*C_*C_;
    long long i = ((long long)blockIdx.x*256 + threadIdx.x)*4;
    if (i >= S) return;
    float4 a = *(const float4*)(P+i);
    float4 b = *(const float4*)(P+S+i);
    float vv[4] = {a.x+b.x, a.y+b.y, a.z+b.z, a.w+b.w};
    __half h[4], l[4];
#pragma unroll
    for (int j=0;j<4;j++){
        h[j] = __float2half_rn(vv[j]);
        l[j] = __float2half_rn(vv[j]-__half2float(h[j]));
    }
    *(__half2*)(F2+i)   = __halves2half2(h[0],h[1]);
    *(__half2*)(F2+i+2) = __halves2half2(h[2],h[3]);
    *(__half2*)(F2+PL_F+i)   = __halves2half2(l[0],l[1]);
    *(__half2*)(F2+PL_F+i+2) = __halves2half2(l[2],l[3]);
}

// ---------------------------------------------------------------------------
// x prep: x -> x2 h/l + rowsum partials. grid (8, 256, 8), block 256
// ---------------------------------------------------------------------------
__global__ void xprep_kernel(const float* __restrict__ x, __half* __restrict__ x2,
                             float* __restrict__ part)
{
    const int b = blockIdx.z;
    const long long boff = (long long)b*C_*N_;
    const int rr = threadIdx.x >> 7;
    const int c  = blockIdx.y*2 + rr;
    const int n0 = blockIdx.x*512 + (threadIdx.x & 127)*4;
    long long o = boff + (long long)c*N_ + n0;
    float4 v = *(const float4*)(x + o);
    __half h0=__float2half_rn(v.x), h1=__float2half_rn(v.y);
    __half h2=__float2half_rn(v.z), h3=__float2half_rn(v.w);
    *(__half2*)(x2+o)   = __halves2half2(h0,h1);
    *(__half2*)(x2+o+2) = __halves2half2(h2,h3);
    *(__half2*)(x2+PL_X+o) =
        __halves2half2(__float2half_rn(v.x-__half2float(h0)),
                       __float2half_rn(v.y-__half2float(h1)));
    *(__half2*)(x2+PL_X+o+2) =
        __halves2half2(__float2half_rn(v.z-__half2float(h2)),
                       __float2half_rn(v.w-__half2float(h3)));
    float rs = v.x + v.y + v.z + v.w;
    const int lane = threadIdx.x & 31;
#pragma unroll
    for (int of=16; of; of>>=1) rs += __shfl_xor_sync(0xffffffffu, rs, of);
    if (!lane){
        int wseg = (threadIdx.x & 127) >> 5;
        part[((long long)(b*C_ + c) << 5) | (blockIdx.x*4 + wseg)] = rs;
    }
}

__global__ void rowsum_reduce(const float* __restrict__ part, float* __restrict__ s)
{
    const int row = blockIdx.x;
    float v = part[((long long)row << 5) | threadIdx.x];
#pragma unroll
    for (int of=16; of; of>>=1) v += __shfl_xor_sync(0xffffffffu, v, of);
    if (!threadIdx.x) s[row] = v;
}

// ---------------------------------------------------------------------------
// Fused: split w_qkv rows 0..2047 (q,k) h/l AND t[b][r] = dot(w_row, s[b]).
// ---------------------------------------------------------------------------
__global__ void wqkv_split_dot(const float* __restrict__ w, const float* __restrict__ s,
                               __half* __restrict__ wqk2, float* __restrict__ t)
{
    const int rr = threadIdx.x >> 7;
    const int r  = blockIdx.x*2 + rr;
    const int ct = (threadIdx.x & 127)*4;
    float4 v = *(const float4*)(w + (long long)r*C_ + ct);

    __half h0=__float2half_rn(v.x), h1=__float2half_rn(v.y);
    __half h2=__float2half_rn(v.z), h3=__float2half_rn(v.w);
    long long o = (long long)r*C_ + ct;
    *(__half2*)(wqk2+o)   = __halves2half2(h0,h1);
    *(__half2*)(wqk2+o+2) = __halves2half2(h2,h3);
    *(__half2*)(wqk2+PL_WQK+o) =
        __halves2half2(__float2half_rn(v.x-__half2float(h0)),
                       __float2half_rn(v.y-__half2float(h1)));
    *(__half2*)(wqk2+PL_WQK+o+2) =
        __halves2half2(__float2half_rn(v.z-__half2float(h2)),
                       __float2half_rn(v.w-__half2float(h3)));

    const int wid = threadIdx.x>>5, lane = threadIdx.x&31;
    __shared__ float sh[8][8];
#pragma unroll
    for (int b=0;b<8;b++){
        float4 sv = *(const float4*)(s + b*C_ + ct);
        float p = v.x*sv.x + v.y*sv.y + v.z*sv.z + v.w*sv.w;
#pragma unroll
        for (int of=16; of; of>>=1) p += __shfl_xor_sync(0xffffffffu, p, of);
        if (!lane) sh[wid][b] = p;
    }
    __syncthreads();
    if (threadIdx.x < 16){
        int r2 = threadIdx.x>>3;
        int b  = threadIdx.x&7;
        float tv = sh[r2*4][b]+sh[r2*4+1][b]+sh[r2*4+2][b]+sh[r2*4+3][b];
        t[b*(3*E_) + blockIdx.x*2 + r2] = tv;
    }
}

// ---------------- conversions (weights) ----------------
__global__ void split2h(const float* __restrict__ s, __half* __restrict__ d,
                        long long plane, long long n)
{
    long long i = ((long long)blockIdx.x*256 + threadIdx.x)*4;
    if (i >= n) return;
    float4 v = *(const float4*)(s+i);
    float vv[4] = {v.x,v.y,v.z,v.w};
    __half h[4], l[4];
#pragma unroll
    for (int j=0;j<4;j++){
        h[j] = __float2half_rn(vv[j]);
        l[j] = __float2half_rn(vv[j]-__half2float(h[j]));
    }
    *(__half2*)(d+i)   = __halves2half2(h[0],h[1]);
    *(__half2*)(d+i+2) = __halves2half2(h[2],h[3]);
    *(__half2*)(d+plane+i)   = __halves2half2(l[0],l[1]);
    *(__half2*)(d+plane+i+2) = __halves2half2(l[2],l[3]);
}

__global__ void tsplit2h(const float* __restrict__ src, __half* __restrict__ dst,
                         int R, int Cc, long long plane, long long ssz, long long dsz)
{
    __shared__ float t[32][33];
    const int z = blockIdx.z;
    src += (long long)z*ssz; dst += (long long)z*dsz;
    const int c0 = blockIdx.x*32, r0 = blockIdx.y*32;
    const int x = threadIdx.x, y = threadIdx.y;
#pragma unroll
    for (int i=0;i<4;i++)
        t[y+8*i][x] = src[(long long)(r0+y+8*i)*Cc + c0 + x];
    __syncthreads();
#pragma unroll
    for (int i=0;i<4;i++){
        float v = t[x][y+8*i];
        __half h = __float2half_rn(v);
        long long o = (long long)(c0+y+8*i)*R + r0 + x;
        dst[o] = h;
        dst[plane+o] = __float2half_rn(v-__half2float(h));
    }
}

// ---------------- small kernels ----------------
__global__ void softmax_kernel(const float* __restrict__ lraw, const float* __restrict__ tvec,
                               const float* __restrict__ bqkv, const float* __restrict__ mask,
                               __half* __restrict__ att2, float* __restrict__ cvec)
{
    const int idx = blockIdx.x;
    const int d = idx&127, h = (idx>>7)&7, b = idx>>10;
    const int e = threadIdx.x;
    const long long base = (long long)idx*D_;
    const long long S = (long long)B_*H_*D_*D_;

    const float bq = bqkv[h*D_+d];
    const float bk = bqkv[E_+h*D_+e];
    const float qt = tvec[b*(3*E_)+h*D_+d];
    const float kt = tvec[b*(3*E_)+E_+h*D_+e];
    float L = lraw[base+e] + lraw[S+base+e] + lraw[2*S+base+e] + lraw[3*S+base+e]
            + bq*kt + bk*qt + (float)N_*bq*bk;

    __shared__ float sh[128];
    sh[e]=L; __syncthreads();
    for (int st=64;st;st>>=1){ if(e<st) sh[e]=fmaxf(sh[e],sh[e+st]); __syncthreads(); }
    const float mx = sh[0]; __syncthreads();
    const float ex = expf(L-mx);
    sh[e]=ex; __syncthreads();
    for (int st=64;st;st>>=1){ if(e<st) sh[e]+=sh[e+st]; __syncthreads(); }
    const float inv = 1.f/sh[0]; __syncthreads();
    const float m = (mask[base+e] < 0.1f) ? 1.f : 0.f;
    const float p = ex*inv*m;

    __half hh = __float2half_rn(p);
    att2[base+e] = hh;
    att2[PL_ATT+base+e] = __float2half_rn(p-__half2float(hh));

    sh[e] = p*bqkv[2*E_+h*D_+e]; __syncthreads();
    for (int st=64;st;st>>=1){ if(e<st) sh[e]+=sh[e+st]; __syncthreads(); }
    if (!e) cvec[b*E_+h*D_+d]=sh[0];
}
__global__ void gvec_kernel(const float* __restrict__ wout, const float* __restrict__ cvec,
                            const float* __restrict__ bout, float* __restrict__ g)
{
    const int cc = blockIdx.x, b = threadIdx.x>>5, lane = threadIdx.x&31;
    const float* wr = wout + (long long)cc*E_;
    const float* cv = cvec + b*E_;
    float acc = 0.f;
    for (int i=lane;i<E_;i+=32) acc += wr[i]*cv[i];
    for (int o=16;o;o>>=1) acc += __shfl_xor_sync(0xffffffffu,acc,o);
    if (!lane) g[b*C_+cc]=acc+bout[cc];
}

// ---------------- launch ----------------
extern "C" void kernel_launch(void* const* d_in, const int* in_sizes, int n_in,
                              void* d_out, int out_size)
{
    const float* x     = (const float*)d_in[0];
    const float* w_qkv = (const float*)d_in[1];
    const float* b_qkv = (const float*)d_in[2];
    const float* w_out = (const float*)d_in[3];
    const float* b_out = (const float*)d_in[4];
    const float* mask  = (const float*)d_in[5];
    float* out = (float*)d_out;

    __half *x2,*wqk2,*wvt2,*wo2,*G2,*A12,*att2,*mt2,*F2;
    float *Gp,*lraw,*part,*s,*t,*cv,*g;
    cudaGetSymbolAddress((void**)&x2,  g_x2);
    cudaGetSymbolAddress((void**)&wqk2,g_wqk2);
    cudaGetSymbolAddress((void**)&wvt2,g_wvt2);
    cudaGetSymbolAddress((void**)&wo2, g_wo2);
    cudaGetSymbolAddress((void**)&G2,  g_G2);
    cudaGetSymbolAddress((void**)&A12, g_A12);
    cudaGetSymbolAddress((void**)&att2,g_att2);
    cudaGetSymbolAddress((void**)&mt2, g_mt2);
    cudaGetSymbolAddress((void**)&F2,  g_F2);
    cudaGetSymbolAddress((void**)&Gp,  g_Gp);
    cudaGetSymbolAddress((void**)&lraw,g_lraw);
    cudaGetSymbolAddress((void**)&part,g_part);
    cudaGetSymbolAddress((void**)&s,   g_s);
    cudaGetSymbolAddress((void**)&t,   g_t);
    cudaGetSymbolAddress((void**)&cv,  g_cv);
    cudaGetSymbolAddress((void**)&g,   g_g);

    const int SMB3  = 2*4*PLB;              // 81920  (NPROD3, 2-stage)
    const int SMB2N = 3*3*PLB;              // 92160  (NPROD2 NT, 3-stage)
    const int SMB1N = 3*2*PLB;              // 61440  (NPROD1 NT, 3-stage)
    const int SMB1T = 3*(PLB + PLBB);       // 56832  (NPROD1 TRB, 3-stage)
    cudaFuncSetAttribute(hgemm<0,false,3,true ,false>, cudaFuncAttributeMaxDynamicSharedMemorySize, SMB3);
    cudaFuncSetAttribute(hgemm<1,false,3,false,false>, cudaFuncAttributeMaxDynamicSharedMemorySize, SMB3);
    cudaFuncSetAttribute(hgemm<0,false,3,false,false>, cudaFuncAttributeMaxDynamicSharedMemorySize, SMB3);
    cudaFuncSetAttribute(hgemm<1,false,1,false,false>, cudaFuncAttributeMaxDynamicSharedMemorySize, SMB1N);
    cudaFuncSetAttribute(hgemm<0,false,2,false,false>, cudaFuncAttributeMaxDynamicSharedMemorySize, SMB2N);
    cudaFuncSetAttribute(hgemm<0,true ,1,false,true >, cudaFuncAttributeMaxDynamicSharedMemorySize, SMB1T);

    const long long CN = (long long)C_*N_;
    const long long CC = (long long)C_*C_;
    const long long EC = (long long)E_*C_;
    const long long DD = (long long)D_*D_;
    const long long DC = (long long)D_*C_;
    const long long S  = (long long)B_*H_*DD;

    // prep
    xprep_kernel<<<dim3(N_/512, C_/2, B_), 256>>>(x, x2, part);
    rowsum_reduce<<<B_*C_, 32>>>(part, s);
    wqkv_split_dot<<<1024, 256>>>(w_qkv, s, wqk2, t);

    // Gram partials: upper tiles, split-K=8 (z = b*8 + ks)
    hgemm<0,false,3,true,false><<<dim3(10,1,B_*8), 256, SMB3>>>(
        x2, x2, Gp, nullptr, N_, N_, N_, C_,
        PL_X, PL_X, 0,
        0, CN,
        0, CN,
        0, CC, (long long)B_*CC,
        0, B_, 8);
    gram_reduce<<<dim3(16,10,B_), dim3(32,8)>>>(Gp, G2);

    // A1[b] = Wq @ G[b]
    hgemm<1,false,3,false,false><<<dim3(4,8,B_), 256, SMB3>>>(
        wqk2, G2, A12, nullptr, C_, C_, C_, C_,
        PL_WQK, PL_G, PL_A1,
        0,0, CC,0, EC,0,0,
        0, 1, 1);

    // logits partials: z = (b*H + h)*4 + ks
    hgemm<0,false,3,false,false><<<dim3(1,1,B_*H_*4), 256, SMB3>>>(
        A12, wqk2 + (long long)E_*C_, lraw, nullptr, C_, C_, C_, D_,
        PL_A1, PL_WQK, 0,
        EC, DC,
        0,  DC,
        (long long)H_*DD, DD, S,
        0, H_, 4);

    // off-path weight conversions (needed from MT onward)
    split2h<<<(int)(PL_WO/4/256), 256>>>(w_out, wo2, PL_WO, PL_WO);
    tsplit2h<<<dim3(C_/32, E_/32, 1), dim3(32,8)>>>(w_qkv + 2LL*E_*C_, wvt2, E_, C_, PL_WVT, 0, 0);

    softmax_kernel<<<B_*H_*D_, 128>>>(lraw, t, b_qkv, mask, att2, cv);

    // MT[b][c, h*128+d] = sum_e WvT[c, h*128+e] * att_h[d,e]   (1-prod, 3-stage)
    hgemm<1,false,1,false,false><<<dim3(1,4,B_*H_), 256, SMB1N>>>(
        wvt2, att2, mt2, nullptr, D_, E_, D_, E_,
        PL_WVT, PL_ATT, PL_MT,
        0, 128,
        (long long)H_*DD, DD,
        (long long)C_*E_, 128, 0,
        0, H_, 1);

    gvec_kernel<<<C_, 256>>>(w_out, cv, b_out, g);

    // F partials: split-K=2 (z = b*2 + ks), fp32 out into Gp (2-prod, 3-stage)
    hgemm<0,false,2,false,false><<<dim3(4,4,B_*2), 256, SMB2N>>>(
        wo2, mt2, Gp, nullptr, E_, E_, E_, C_,
        PL_WO, PL_MT, 0,
        0, 0,
        (long long)C_*E_, 0,
        CC, 0, (long long)B_*CC,
        0, 1, 2);
    freduce<<<(int)((B_*CC/4 + 255)/256), 256>>>(Gp, F2);

    // out[b] = F[b] @ x[b] + g   (TN, 1-prod, 3-stage)
    hgemm<0,true,1,false,true><<<dim3(32,4,B_), 256, SMB1T>>>(
        F2, x2, out, g, C_, C_, N_, N_,
        PL_F, PL_X, 0,
        CC,0, CN,0, CN,0,0,
        C_, 1, 1);
}

// round 17
// speedup vs baseline: 1.1731x; 1.0495x over previous
#include <cuda_runtime.h>
#include <cuda_fp16.h>
#include <cstdint>

#define B_ 8
#define C_ 512
#define N_ 4096
#define E_ 1024
#define H_ 8
#define D_ 128

#define PL_X   (8LL*512*4096)
#define PL_WQK (2048LL*512)
#define PL_WVT (512LL*1024)
#define PL_WO  (512LL*1024)
#define PL_G   (8LL*512*512)
#define PL_A1  (8LL*1024*512)
#define PL_ATT (8LL*8*128*128)
#define PL_MT  (8LL*512*1024)
#define PL_F   (8LL*512*512)

__device__ __half g_x2  [2*PL_X];
__device__ __half g_wqk2[2*PL_WQK];
__device__ __half g_wvt2[2*PL_WVT];
__device__ __half g_wo2 [2*PL_WO];
__device__ __half g_G2  [2*PL_G];
__device__ __half g_A12 [2*PL_A1];
__device__ __half g_att2[2*PL_ATT];
__device__ __half g_mt2 [2*PL_MT];
__device__ __half g_F2  [2*PL_F];
__device__ float g_Gp  [8*B_*C_*C_];
__device__ float g_lraw[4*B_*H_*D_*D_];
__device__ float g_part[B_*C_*128];
__device__ float g_s [B_*C_];
__device__ float g_t [B_*3*E_];
__device__ float g_cv[B_*E_];
__device__ float g_g [B_*C_];

__device__ __forceinline__ uint32_t smem_u32(const void* p){
    uint32_t a;
    asm("{ .reg .u64 t; cvta.to.shared.u64 t, %1; cvt.u32.u64 %0, t; }":"=r"(a):"l"(p));
    return a;
}
#define CP16(dst, src) asm volatile("cp.async.cg.shared.global [%0], [%1], 16;"::"r"(dst),"l"(src))
#define CP_COMMIT() asm volatile("cp.async.commit_group;")
#define CP_WAIT2() asm volatile("cp.async.wait_group 2;")
#define CP_WAIT1() asm volatile("cp.async.wait_group 1;")
#define CP_WAIT0() asm volatile("cp.async.wait_group 0;")
#define LDSM4(R, A) \
    asm volatile("ldmatrix.sync.aligned.m8n8.x4.shared.b16 {%0,%1,%2,%3}, [%4];" \
        : "=r"((R)[0]),"=r"((R)[1]),"=r"((R)[2]),"=r"((R)[3]) : "r"(A))
#define LDSM4T(R, A) \
    asm volatile("ldmatrix.sync.aligned.m8n8.x4.trans.shared.b16 {%0,%1,%2,%3}, [%4];" \
        : "=r"((R)[0]),"=r"((R)[1]),"=r"((R)[2]),"=r"((R)[3]) : "r"(A))
#define MMA(C, A, B0, B1) \
    asm volatile("mma.sync.aligned.m16n8k16.row.col.f32.f16.f16.f32 " \
        "{%0,%1,%2,%3}, {%4,%5,%6,%7}, {%8,%9}, {%0,%1,%2,%3};" \
        : "+f"((C)[0]),"+f"((C)[1]),"+f"((C)[2]),"+f"((C)[3]) \
        : "r"((A)[0]),"r"((A)[1]),"r"((A)[2]),"r"((A)[3]), "r"(B0),"r"(B1))

// ---------------------------------------------------------------------------
// fp16-split GEMM, 128x128 CTA tile, BK=32, 256 thr, warp 64x32, 2 CTAs/SM.
// NPROD=3: hh+hl+lh (4 planes, 2-stage). NPROD=2: hh+hl (3 planes, 3-stage).
// NPROD=1: hh only (2 planes, 4-stage, 2 chunks per sync-pair; even #chunks).
// TRB: B is (K,N), ldmatrix.trans. SYM: upper-tri tiles of 512x512.
// OUTP 0: fp32 (+bias row if HB). OUTP 1: 2-plane fp16. OUTP 2: hi plane only.
// ZBi = K-split: piece zi covers chunks [zi*nch/ZBi, (zi+1)*nch/ZBi).
// ---------------------------------------------------------------------------
#define PITCH 80
#define PLB (128*PITCH)
#define PITCHB 272
#define PLBB (32*PITCHB)

template <int OUTP, bool HB, int NPROD, bool SYM, bool TRB>
__global__ void __launch_bounds__(256, 2)
hgemm(const __half* __restrict__ A, const __half* __restrict__ B,
      void* __restrict__ Cv, const float* __restrict__ bias,
      int K, int lda, int ldb, int ldc,
      long long planeA, long long planeB, long long planeC,
      long long sAo, long long sAm,
      long long sBo, long long sBm,
      long long sCo, long long sCm, long long sCi,
      long long sBias, int ZBm, int ZBi)
{
    constexpr int NSTAGE = (NPROD==1) ? 4 : ((NPROD==2) ? 3 : 2);
    constexpr int NBPL   = (NPROD==1) ? 1 : 2;        // B planes
    constexpr int BBASE  = (NPROD==3) ? 2*PLB : PLB;  // A-plane bytes
    constexpr int SBP    = TRB ? PLBB : PLB;
    constexpr int BUFS   = BBASE + NBPL*SBP;

    extern __shared__ char smem[];
    const uint32_t sb = smem_u32(smem);
    const int tid = threadIdx.x, wid = tid>>5, lane = tid&31;
    const int z = blockIdx.z;
    const int zo = z/(ZBm*ZBi);
    const int zr = z - zo*ZBm*ZBi;
    const int zm = zr/ZBi;
    const int zi = zr - zm*ZBi;
    A += zo*sAo + zm*sAm;
    B += zo*sBo + zm*sBm;
    const long long co = zo*sCo + zm*sCm + zi*sCi;

    int bx = blockIdx.x, by = blockIdx.y;
    if (SYM){
        int i = blockIdx.x;
        int tx = 0;
        while (((tx+1)*(tx+2))/2 <= i) tx++;
        by = i - (tx*(tx+1))/2;
        bx = tx;
    }
    const int row0 = by*128, col0 = bx*128;

    const __half* gp[4] = {A, A+planeA, B, B+planeB};
    const int gld[4]  = {lda, lda, ldb, ldb};
    const int gr0[4]  = {row0, row0, col0, col0};

    const int wm0 = (wid&1)*64;
    const int wn0 = (wid>>1)*32;

    int aoff[4], boff[2];
    int boffT = 0;
#pragma unroll
    for (int mt=0; mt<4; mt++){
        int r = wm0 + mt*16 + ((lane>>3)&1)*8 + (lane&7);
        aoff[mt] = r*PITCH + ((lane>>4)&1)*16;
    }
    if (TRB){
        boffT = (((lane>>3)&1)*8 + (lane&7))*PITCHB + wn0*2 + ((lane>>4)&1)*16;
    } else {
#pragma unroll
        for (int ng=0; ng<2; ng++){
            int r = wn0 + ng*16 + ((lane>>4)&1)*8 + (lane&7);
            boff[ng] = r*PITCH + ((lane>>3)&1)*16;
        }
    }

    float acc[4][4][4];
#pragma unroll
    for (int i=0;i<4;i++)
#pragma unroll
        for (int j=0;j<4;j++)
#pragma unroll
            for (int k=0;k<4;k++) acc[i][j][k]=0.f;

#define LOADCH(CH, BUF) do{ \
    int kk = (CH)<<5; \
    _Pragma("unroll") \
    for (int p=0;p<4;p++){ \
        if (NPROD<=2 && p==1) continue; \
        if (NPROD==1 && p==3) continue; \
        const int slot = (p==0)?0 : (p==1)?PLB : BBASE + (p-2)*SBP; \
        if (TRB && p>=2){ \
            _Pragma("unroll") \
            for (int j=0;j<2;j++){ \
                int idx = j*256 + tid; \
                int r = idx>>4, c = idx&15; \
                uint32_t dst = sb + (BUF)*BUFS + slot + r*PITCHB + c*16; \
                const __half* src = gp[p] + (long long)(kk+r)*gld[p] + col0 + c*8; \
                CP16(dst, src); \
            } \
        } else { \
            _Pragma("unroll") \
            for (int j=0;j<2;j++){ \
                int idx = j*256 + tid; \
                int r = idx>>2, c = idx&3; \
                uint32_t dst = sb + (BUF)*BUFS + slot + r*PITCH + c*16; \
                const __half* src = gp[p] + (long long)(gr0[p]+r)*gld[p] + kk + c*8; \
                CP16(dst, src); \
            } \
        } \
    } \
}while(0)

#define CONSUME(BUFI) do{ \
    const uint32_t bufb = sb + (BUFI)*BUFS; \
    _Pragma("unroll") \
    for (int ks=0; ks<2; ks++){ \
        uint32_t af0[4][4], af1[4][4], bf[2][2][4]; \
        _Pragma("unroll") \
        for (int mt=0;mt<4;mt++) \
            LDSM4(af0[mt], bufb + aoff[mt] + ks*32); \
        _Pragma("unroll") \
        for (int p=0;p<NBPL;p++) \
            _Pragma("unroll") \
            for (int ng=0;ng<2;ng++){ \
                if (TRB) \
                    LDSM4T(bf[p][ng], bufb + BBASE + p*SBP + boffT + ks*(16*PITCHB) + ng*32); \
                else \
                    LDSM4(bf[p][ng], bufb + BBASE + p*SBP + boff[ng] + ks*32); \
            } \
        _Pragma("unroll") \
        for (int mt=0;mt<4;mt++) \
            _Pragma("unroll") \
            for (int nt=0;nt<4;nt++) \
                MMA(acc[mt][nt], af0[mt], bf[0][nt>>1][(nt&1)*2], bf[0][nt>>1][(nt&1)*2+1]); \
        if (NPROD==3) \
            _Pragma("unroll") \
            for (int mt=0;mt<4;mt++) \
                LDSM4(af1[mt], bufb + PLB + aoff[mt] + ks*32); \
        if (NPROD>=2) \
            _Pragma("unroll") \
            for (int mt=0;mt<4;mt++) \
                _Pragma("unroll") \
                for (int nt=0;nt<4;nt++) \
                    MMA(acc[mt][nt], af0[mt], bf[1][nt>>1][(nt&1)*2], bf[1][nt>>1][(nt&1)*2+1]); \
        if (NPROD==3) \
            _Pragma("unroll") \
            for (int mt=0;mt<4;mt++) \
                _Pragma("unroll") \
                for (int nt=0;nt<4;nt++) \
                    MMA(acc[mt][nt], af1[mt], bf[0][nt>>1][(nt&1)*2], bf[0][nt>>1][(nt&1)*2+1]); \
    } \
}while(0)

    const int nchT = K>>5;
    const int c0 = (zi*nchT)/ZBi;
    const int c1 = ((zi+1)*nchT)/ZBi;

    if (NPROD==1){
        // even chunk count; 4 stages; 2 chunks per sync-pair
        LOADCH(c0,0);   CP_COMMIT();
        LOADCH(c0+1,1); CP_COMMIT();
        for (int ch=c0; ch<c1; ch+=2){
            if (ch+2 < c1){
                LOADCH(ch+2, (ch-c0+2)&3); CP_COMMIT();
                LOADCH(ch+3, (ch-c0+3)&3); CP_COMMIT();
                CP_WAIT2();
            } else CP_WAIT0();
            __syncthreads();
            CONSUME((ch-c0)&3);
            CONSUME((ch-c0+1)&3);
            __syncthreads();
        }
    } else {
        LOADCH(c0,0); CP_COMMIT();
        if (NSTAGE==3 && c0+1 < c1){ LOADCH(c0+1,1); CP_COMMIT(); }
        for (int ch=c0; ch<c1; ++ch){
            const int bufi = (ch-c0)%NSTAGE;
            if (NSTAGE==3){
                if (ch+2 < c1){
                    LOADCH(ch+2, (ch-c0+2)%3); CP_COMMIT();
                    CP_WAIT2();
                } else if (ch+1 < c1) CP_WAIT1();
                else CP_WAIT0();
            } else {
                if (ch+1 < c1){
                    LOADCH(ch+1, bufi^1); CP_COMMIT();
                    CP_WAIT1();
                } else CP_WAIT0();
            }
            __syncthreads();
            CONSUME(bufi);
            __syncthreads();
        }
    }

    // epilogue
#pragma unroll
    for (int mt=0;mt<4;mt++){
#pragma unroll
        for (int nt=0;nt<4;nt++){
            int r0 = row0 + wm0 + mt*16 + (lane>>2);
            int cb = col0 + wn0 + nt*8 + (lane&3)*2;
            if (OUTP == 0){
                float* Cf = (float*)Cv + co;
                float b0 = HB ? bias[(long long)zo*sBias + r0]     : 0.f;
                float b1 = HB ? bias[(long long)zo*sBias + r0 + 8] : 0.f;
                *(float2*)(Cf + (long long)r0*ldc + cb) =
                    make_float2(acc[mt][nt][0]+b0, acc[mt][nt][1]+b0);
                *(float2*)(Cf + (long long)(r0+8)*ldc + cb) =
                    make_float2(acc[mt][nt][2]+b1, acc[mt][nt][3]+b1);
            } else if (OUTP == 1){
                __half* Ch = (__half*)Cv + co;
#pragma unroll
                for (int hrow=0; hrow<2; hrow++){
                    long long o = (long long)(r0 + hrow*8)*ldc + cb;
                    float v0 = acc[mt][nt][hrow*2], v1 = acc[mt][nt][hrow*2+1];
                    __half h0 = __float2half_rn(v0), h1 = __float2half_rn(v1);
                    __half l0 = __float2half_rn(v0-__half2float(h0));
                    __half l1 = __float2half_rn(v1-__half2float(h1));
                    *(__half2*)(Ch + o) = __halves2half2(h0,h1);
                    *(__half2*)(Ch + planeC + o) = __halves2half2(l0,l1);
                }
            } else {  // OUTP == 2: hi plane only
                __half* Ch = (__half*)Cv + co;
#pragma unroll
                for (int hrow=0; hrow<2; hrow++){
                    long long o = (long long)(r0 + hrow*8)*ldc + cb;
                    *(__half2*)(Ch + o) =
                        __halves2half2(__float2half_rn(acc[mt][nt][hrow*2]),
                                       __float2half_rn(acc[mt][nt][hrow*2+1]));
                }
            }
        }
    }
#undef LOADCH
#undef CONSUME
}

// ---------------------------------------------------------------------------
// Gram reduce: sum 8 fp32 split-K partials (upper tiles), split fp16 h/l,
// mirror lower triangle. grid (16, 10, 8), block (32,8)
// ---------------------------------------------------------------------------
__global__ void gram_reduce(const float* __restrict__ P, __half* __restrict__ G2)
{
    const int RY[10]={0,0,1,0,1,2,0,1,2,3};
    const int CX[10]={0,1,1,2,2,2,3,3,3,3};
    const int t = blockIdx.y, b = blockIdx.z;
    const int r0 = RY[t]*128 + (blockIdx.x>>2)*32;
    const int c0 = CX[t]*128 + (blockIdx.x&3)*32;
    const long long CC = (long long)C_*C_;
    const long long S = (long long)B_*CC;
    const float* Pb = P + (long long)b*CC;
    __half* Gb = G2 + (long long)b*CC;
    __shared__ __half th[32][33], tl_[32][33];
    const int x = threadIdx.x, y = threadIdx.y;
#pragma unroll
    for (int i=0;i<4;i++){
        int r = r0 + y + 8*i;
        long long o = (long long)r*C_ + c0 + x;
        float v = 0.f;
#pragma unroll
        for (int p=0;p<8;p++) v += Pb[p*S + o];
        __half h = __float2half_rn(v);
        __half l = __float2half_rn(v - __half2float(h));
        Gb[o] = h;
        Gb[PL_G + o] = l;
        th[y+8*i][x] = h;
        tl_[y+8*i][x] = l;
    }
    __syncthreads();
    if (RY[t] != CX[t]){
#pragma unroll
        for (int i=0;i<4;i++){
            long long o = (long long)(c0+y+8*i)*C_ + r0 + x;
            Gb[o] = th[x][y+8*i];
            Gb[PL_G + o] = tl_[x][y+8*i];
        }
    }
}

// F reduce: sum 2 fp32 partials -> F2 hi plane only (out GEMM is 1-prod).
__global__ void freduce(const float* __restrict__ P, __half* __restrict__ F2)
{
    const long long S = (long long)B_*C_*C_;
    long long i = ((long long)blockIdx.x*256 + threadIdx.x)*4;
    if (i >= S) return;
    float4 a = *(const float4*)(P+i);
    float4 b = *(const float4*)(P+S+i);
    *(__half2*)(F2+i)   = __halves2half2(__float2half_rn(a.x+b.x), __float2half_rn(a.y+b.y));
    *(__half2*)(F2+i+2) = __halves2half2(__float2half_rn(a.z+b.z), __float2half_rn(a.w+b.w));
}

// ---------------------------------------------------------------------------
// x prep: x -> x2 h/l + rowsum partials. grid (8, 256, 8), block 256
// ---------------------------------------------------------------------------
__global__ void xprep_kernel(const float* __restrict__ x, __half* __restrict__ x2,
                             float* __restrict__ part)
{
    const int b = blockIdx.z;
    const long long boff = (long long)b*C_*N_;
    const int rr = threadIdx.x >> 7;
    const int c  = blockIdx.y*2 + rr;
    const int n0 = blockIdx.x*512 + (threadIdx.x & 127)*4;
    long long o = boff + (long long)c*N_ + n0;
    float4 v = *(const float4*)(x + o);
    __half h0=__float2half_rn(v.x), h1=__float2half_rn(v.y);
    __half h2=__float2half_rn(v.z), h3=__float2half_rn(v.w);
    *(__half2*)(x2+o)   = __halves2half2(h0,h1);
    *(__half2*)(x2+o+2) = __halves2half2(h2,h3);
    *(__half2*)(x2+PL_X+o) =
        __halves2half2(__float2half_rn(v.x-__half2float(h0)),
                       __float2half_rn(v.y-__half2float(h1)));
    *(__half2*)(x2+PL_X+o+2) =
        __halves2half2(__float2half_rn(v.z-__half2float(h2)),
                       __float2half_rn(v.w-__half2float(h3)));
    float rs = v.x + v.y + v.z + v.w;
    const int lane = threadIdx.x & 31;
#pragma unroll
    for (int of=16; of; of>>=1) rs += __shfl_xor_sync(0xffffffffu, rs, of);
    if (!lane){
        int wseg = (threadIdx.x & 127) >> 5;
        part[((long long)(b*C_ + c) << 5) | (blockIdx.x*4 + wseg)] = rs;
    }
}

__global__ void rowsum_reduce(const float* __restrict__ part, float* __restrict__ s)
{
    const int row = blockIdx.x;
    float v = part[((long long)row << 5) | threadIdx.x];
#pragma unroll
    for (int of=16; of; of>>=1) v += __shfl_xor_sync(0xffffffffu, v, of);
    if (!threadIdx.x) s[row] = v;
}

// ---------------------------------------------------------------------------
// Fused: split w_qkv rows 0..2047 (q,k) h/l AND t[b][r] = dot(w_row, s[b]).
// ---------------------------------------------------------------------------
__global__ void wqkv_split_dot(const float* __restrict__ w, const float* __restrict__ s,
                               __half* __restrict__ wqk2, float* __restrict__ t)
{
    const int rr = threadIdx.x >> 7;
    const int r  = blockIdx.x*2 + rr;
    const int ct = (threadIdx.x & 127)*4;
    float4 v = *(const float4*)(w + (long long)r*C_ + ct);

    __half h0=__float2half_rn(v.x), h1=__float2half_rn(v.y);
    __half h2=__float2half_rn(v.z), h3=__float2half_rn(v.w);
    long long o = (long long)r*C_ + ct;
    *(__half2*)(wqk2+o)   = __halves2half2(h0,h1);
    *(__half2*)(wqk2+o+2) = __halves2half2(h2,h3);
    *(__half2*)(wqk2+PL_WQK+o) =
        __halves2half2(__float2half_rn(v.x-__half2float(h0)),
                       __float2half_rn(v.y-__half2float(h1)));
    *(__half2*)(wqk2+PL_WQK+o+2) =
        __halves2half2(__float2half_rn(v.z-__half2float(h2)),
                       __float2half_rn(v.w-__half2float(h3)));

    const int wid = threadIdx.x>>5, lane = threadIdx.x&31;
    __shared__ float sh[8][8];
#pragma unroll
    for (int b=0;b<8;b++){
        float4 sv = *(const float4*)(s + b*C_ + ct);
        float p = v.x*sv.x + v.y*sv.y + v.z*sv.z + v.w*sv.w;
#pragma unroll
        for (int of=16; of; of>>=1) p += __shfl_xor_sync(0xffffffffu, p, of);
        if (!lane) sh[wid][b] = p;
    }
    __syncthreads();
    if (threadIdx.x < 16){
        int r2 = threadIdx.x>>3;
        int b  = threadIdx.x&7;
        float tv = sh[r2*4][b]+sh[r2*4+1][b]+sh[r2*4+2][b]+sh[r2*4+3][b];
        t[b*(3*E_) + blockIdx.x*2 + r2] = tv;
    }
}

// ---------------- conversions (weights) ----------------
__global__ void split2h(const float* __restrict__ s, __half* __restrict__ d,
                        long long plane, long long n)
{
    long long i = ((long long)blockIdx.x*256 + threadIdx.x)*4;
    if (i >= n) return;
    float4 v = *(const float4*)(s+i);
    float vv[4] = {v.x,v.y,v.z,v.w};
    __half h[4], l[4];
#pragma unroll
    for (int j=0;j<4;j++){
        h[j] = __float2half_rn(vv[j]);
        l[j] = __float2half_rn(vv[j]-__half2float(h[j]));
    }
    *(__half2*)(d+i)   = __halves2half2(h[0],h[1]);
    *(__half2*)(d+i+2) = __halves2half2(h[2],h[3]);
    *(__half2*)(d+plane+i)   = __halves2half2(l[0],l[1]);
    *(__half2*)(d+plane+i+2) = __halves2half2(l[2],l[3]);
}

__global__ void tsplit2h(const float* __restrict__ src, __half* __restrict__ dst,
                         int R, int Cc, long long plane, long long ssz, long long dsz)
{
    __shared__ float t[32][33];
    const int z = blockIdx.z;
    src += (long long)z*ssz; dst += (long long)z*dsz;
    const int c0 = blockIdx.x*32, r0 = blockIdx.y*32;
    const int x = threadIdx.x, y = threadIdx.y;
#pragma unroll
    for (int i=0;i<4;i++)
        t[y+8*i][x] = src[(long long)(r0+y+8*i)*Cc + c0 + x];
    __syncthreads();
#pragma unroll
    for (int i=0;i<4;i++){
        float v = t[x][y+8*i];
        __half h = __float2half_rn(v);
        long long o = (long long)(c0+y+8*i)*R + r0 + x;
        dst[o] = h;
        dst[plane+o] = __float2half_rn(v-__half2float(h));
    }
}

// ---------------- small kernels ----------------
__global__ void softmax_kernel(const float* __restrict__ lraw, const float* __restrict__ tvec,
                               const float* __restrict__ bqkv, const float* __restrict__ mask,
                               __half* __restrict__ att2, float* __restrict__ cvec)
{
    const int idx = blockIdx.x;
    const int d = idx&127, h = (idx>>7)&7, b = idx>>10;
    const int e = threadIdx.x;
    const long long base = (long long)idx*D_;
    const long long S = (long long)B_*H_*D_*D_;

    const float bq = bqkv[h*D_+d];
    const float bk = bqkv[E_+h*D_+e];
    const float qt = tvec[b*(3*E_)+h*D_+d];
    const float kt = tvec[b*(3*E_)+E_+h*D_+e];
    float L = lraw[base+e] + lraw[S+base+e] + lraw[2*S+base+e] + lraw[3*S+base+e]
            + bq*kt + bk*qt + (float)N_*bq*bk;

    __shared__ float sh[128];
    sh[e]=L; __syncthreads();
    for (int st=64;st;st>>=1){ if(e<st) sh[e]=fmaxf(sh[e],sh[e+st]); __syncthreads(); }
    const float mx = sh[0]; __syncthreads();
    const float ex = expf(L-mx);
    sh[e]=ex; __syncthreads();
    for (int st=64;st;st>>=1){ if(e<st) sh[e]+=sh[e+st]; __syncthreads(); }
    const float inv = 1.f/sh[0]; __syncthreads();
    const float m = (mask[base+e] < 0.1f) ? 1.f : 0.f;
    const float p = ex*inv*m;

    __half hh = __float2half_rn(p);
    att2[base+e] = hh;
    att2[PL_ATT+base+e] = __float2half_rn(p-__half2float(hh));

    sh[e] = p*bqkv[2*E_+h*D_+e]; __syncthreads();
    for (int st=64;st;st>>=1){ if(e<st) sh[e]+=sh[e+st]; __syncthreads(); }
    if (!e) cvec[b*E_+h*D_+d]=sh[0];
}
__global__ void gvec_kernel(const float* __restrict__ wout, const float* __restrict__ cvec,
                            const float* __restrict__ bout, float* __restrict__ g)
{
    const int cc = blockIdx.x, b = threadIdx.x>>5, lane = threadIdx.x&31;
    const float* wr = wout + (long long)cc*E_;
    const float* cv = cvec + b*E_;
    float acc = 0.f;
    for (int i=lane;i<E_;i+=32) acc += wr[i]*cv[i];
    for (int o=16;o;o>>=1) acc += __shfl_xor_sync(0xffffffffu,acc,o);
    if (!lane) g[b*C_+cc]=acc+bout[cc];
}

// ---------------- launch ----------------
extern "C" void kernel_launch(void* const* d_in, const int* in_sizes, int n_in,
                              void* d_out, int out_size)
{
    const float* x     = (const float*)d_in[0];
    const float* w_qkv = (const float*)d_in[1];
    const float* b_qkv = (const float*)d_in[2];
    const float* w_out = (const float*)d_in[3];
    const float* b_out = (const float*)d_in[4];
    const float* mask  = (const float*)d_in[5];
    float* out = (float*)d_out;

    __half *x2,*wqk2,*wvt2,*wo2,*G2,*A12,*att2,*mt2,*F2;
    float *Gp,*lraw,*part,*s,*t,*cv,*g;
    cudaGetSymbolAddress((void**)&x2,  g_x2);
    cudaGetSymbolAddress((void**)&wqk2,g_wqk2);
    cudaGetSymbolAddress((void**)&wvt2,g_wvt2);
    cudaGetSymbolAddress((void**)&wo2, g_wo2);
    cudaGetSymbolAddress((void**)&G2,  g_G2);
    cudaGetSymbolAddress((void**)&A12, g_A12);
    cudaGetSymbolAddress((void**)&att2,g_att2);
    cudaGetSymbolAddress((void**)&mt2, g_mt2);
    cudaGetSymbolAddress((void**)&F2,  g_F2);
    cudaGetSymbolAddress((void**)&Gp,  g_Gp);
    cudaGetSymbolAddress((void**)&lraw,g_lraw);
    cudaGetSymbolAddress((void**)&part,g_part);
    cudaGetSymbolAddress((void**)&s,   g_s);
    cudaGetSymbolAddress((void**)&t,   g_t);
    cudaGetSymbolAddress((void**)&cv,  g_cv);
    cudaGetSymbolAddress((void**)&g,   g_g);

    const int SMB3  = 2*4*PLB;              // 81920  (NPROD3, 2-stage)
    const int SMB1N = 4*2*PLB;              // 81920  (NPROD1 NT, 4-stage)
    const int SMB1T = 4*(PLB + PLBB);       // 75776  (NPROD1 TRB, 4-stage)
    cudaFuncSetAttribute(hgemm<0,false,3,true ,false>, cudaFuncAttributeMaxDynamicSharedMemorySize, SMB3);
    cudaFuncSetAttribute(hgemm<1,false,3,false,false>, cudaFuncAttributeMaxDynamicSharedMemorySize, SMB3);
    cudaFuncSetAttribute(hgemm<0,false,3,false,false>, cudaFuncAttributeMaxDynamicSharedMemorySize, SMB3);
    cudaFuncSetAttribute(hgemm<2,false,1,false,false>, cudaFuncAttributeMaxDynamicSharedMemorySize, SMB1N);
    cudaFuncSetAttribute(hgemm<0,false,1,false,false>, cudaFuncAttributeMaxDynamicSharedMemorySize, SMB1N);
    cudaFuncSetAttribute(hgemm<0,true ,1,false,true >, cudaFuncAttributeMaxDynamicSharedMemorySize, SMB1T);

    const long long CN = (long long)C_*N_;
    const long long CC = (long long)C_*C_;
    const long long EC = (long long)E_*C_;
    const long long DD = (long long)D_*D_;
    const long long DC = (long long)D_*C_;
    const long long S  = (long long)B_*H_*DD;

    // prep
    xprep_kernel<<<dim3(N_/512, C_/2, B_), 256>>>(x, x2, part);
    rowsum_reduce<<<B_*C_, 32>>>(part, s);
    wqkv_split_dot<<<1024, 256>>>(w_qkv, s, wqk2, t);

    // Gram partials: upper tiles, split-K=8 (z = b*8 + ks)
    hgemm<0,false,3,true,false><<<dim3(10,1,B_*8), 256, SMB3>>>(
        x2, x2, Gp, nullptr, N_, N_, N_, C_,
        PL_X, PL_X, 0,
        0, CN,
        0, CN,
        0, CC, (long long)B_*CC,
        0, B_, 8);
    gram_reduce<<<dim3(16,10,B_), dim3(32,8)>>>(Gp, G2);

    // A1[b] = Wq @ G[b]
    hgemm<1,false,3,false,false><<<dim3(4,8,B_), 256, SMB3>>>(
        wqk2, G2, A12, nullptr, C_, C_, C_, C_,
        PL_WQK, PL_G, PL_A1,
        0,0, CC,0, EC,0,0,
        0, 1, 1);

    // logits partials: z = (b*H + h)*4 + ks
    hgemm<0,false,3,false,false><<<dim3(1,1,B_*H_*4), 256, SMB3>>>(
        A12, wqk2 + (long long)E_*C_, lraw, nullptr, C_, C_, C_, D_,
        PL_A1, PL_WQK, 0,
        EC, DC,
        0,  DC,
        (long long)H_*DD, DD, S,
        0, H_, 4);

    // off-path weight conversions (needed from MT onward)
    split2h<<<(int)(PL_WO/4/256), 256>>>(w_out, wo2, PL_WO, PL_WO);
    tsplit2h<<<dim3(C_/32, E_/32, 1), dim3(32,8)>>>(w_qkv + 2LL*E_*C_, wvt2, E_, C_, PL_WVT, 0, 0);

    softmax_kernel<<<B_*H_*D_, 128>>>(lraw, t, b_qkv, mask, att2, cv);

    // MT[b][c, h*128+d] = sum_e WvT[c, h*128+e] * att_h[d,e]  (1-prod, hi out)
    hgemm<2,false,1,false,false><<<dim3(1,4,B_*H_), 256, SMB1N>>>(
        wvt2, att2, mt2, nullptr, D_, E_, D_, E_,
        PL_WVT, PL_ATT, 0,
        0, 128,
        (long long)H_*DD, DD,
        (long long)C_*E_, 128, 0,
        0, H_, 1);

    gvec_kernel<<<C_, 256>>>(w_out, cv, b_out, g);

    // F partials: split-K=2 (z = b*2 + ks), fp32 out into Gp (1-prod)
    hgemm<0,false,1,false,false><<<dim3(4,4,B_*2), 256, SMB1N>>>(
        wo2, mt2, Gp, nullptr, E_, E_, E_, C_,
        PL_WO, PL_MT, 0,
        0, 0,
        (long long)C_*E_, 0,
        CC, 0, (long long)B_*CC,
        0, 1, 2);
    freduce<<<(int)((B_*CC/4 + 255)/256), 256>>>(Gp, F2);

    // out[b] = F[b] @ x[b] + g   (TN, 1-prod, 4-stage)
    hgemm<0,true,1,false,true><<<dim3(32,4,B_), 256, SMB1T>>>(
        F2, x2, out, g, C_, C_, N_, N_,
        PL_F, PL_X, 0,
        CC,0, CN,0, CN,0,0,
        C_, 1, 1);
}